// round 1
// baseline (speedup 1.0000x reference)
#include <cuda_runtime.h>
#include <math.h>

#define SEQ   2048
#define NTOK  4096
#define ED    1024
#define KVD   256
#define HD    128
#define KI    256   // ints per activation row (ED/4)

// ---------------- device scratch (no allocations allowed) ----------------
__device__ float g_alpha[4];
__device__ float g_part[4][128];
__device__ signed char g_sq[ED*ED];
__device__ signed char g_sk[KVD*ED];
__device__ signed char g_sv[KVD*ED];
__device__ signed char g_so[ED*ED];
__device__ signed char g_nact[NTOK*ED];
__device__ float g_fact[NTOK];
__device__ float g_q[NTOK*ED];
__device__ float g_k[NTOK*KVD];
__device__ float g_v[NTOK*KVD];
__device__ float g_x[NTOK*ED];

__device__ __forceinline__ signed char* sel_sign(int m) {
    return m == 0 ? g_sq : m == 1 ? g_sk : m == 2 ? g_sv : g_so;
}

// ---------------- weight prep: mean|w| and sign pack ----------------
__global__ void absmean_partial(const float* __restrict__ w, int n, int mid) {
    __shared__ float sh[256];
    float s = 0.f;
    for (int i = blockIdx.x * blockDim.x + threadIdx.x; i < n; i += gridDim.x * blockDim.x)
        s += fabsf(w[i]);
    sh[threadIdx.x] = s;
    __syncthreads();
    for (int o = 128; o > 0; o >>= 1) {
        if (threadIdx.x < o) sh[threadIdx.x] += sh[threadIdx.x + o];
        __syncthreads();
    }
    if (threadIdx.x == 0) g_part[mid][blockIdx.x] = sh[0];
}

__global__ void absmean_final() {
    int m = threadIdx.x >> 5, l = threadIdx.x & 31;
    float s = g_part[m][l] + g_part[m][l + 32] + g_part[m][l + 64] + g_part[m][l + 96];
    #pragma unroll
    for (int o = 16; o; o >>= 1) s += __shfl_xor_sync(0xffffffffu, s, o);
    if (l == 0) {
        float n = (m == 1 || m == 2) ? (float)(KVD * ED) : (float)(ED * ED);
        g_alpha[m] = s / n;
    }
}

__global__ void sign_pack(const float* __restrict__ w, int mid, int n4) {
    int i = blockIdx.x * blockDim.x + threadIdx.x;
    if (i >= n4) return;
    float4 v = ((const float4*)w)[i];
    char4 c;
    c.x = (signed char)((v.x > 0.f) - (v.x < 0.f));
    c.y = (signed char)((v.y > 0.f) - (v.y < 0.f));
    c.z = (signed char)((v.z > 0.f) - (v.z < 0.f));
    c.w = (signed char)((v.w > 0.f) - (v.w < 0.f));
    ((char4*)sel_sign(mid))[i] = c;
}

// ---------------- RMSNorm + activation quant (per token) ----------------
__global__ void quant_rms(const float* __restrict__ x) {
    int t = blockIdx.x, tid = threadIdx.x;
    const float4* xr = (const float4*)(x + (size_t)t * ED);
    float4 v = xr[tid];
    float ss = v.x * v.x + v.y * v.y + v.z * v.z + v.w * v.w;
    float am = fmaxf(fmaxf(fabsf(v.x), fabsf(v.y)), fmaxf(fabsf(v.z), fabsf(v.w)));
    #pragma unroll
    for (int o = 16; o; o >>= 1) {
        ss += __shfl_xor_sync(0xffffffffu, ss, o);
        am = fmaxf(am, __shfl_xor_sync(0xffffffffu, am, o));
    }
    __shared__ float sa[8], sb[8];
    int w = tid >> 5, l = tid & 31;
    if (l == 0) { sa[w] = ss; sb[w] = am; }
    __syncthreads();
    float sst = 0.f, amt = 0.f;
    #pragma unroll
    for (int i = 0; i < 8; i++) { sst += sa[i]; amt = fmaxf(amt, sb[i]); }
    float r = 1.f / (sqrtf(sst * (1.f / ED) + 1e-6f) * 32.f);
    float scale = 127.f / fmaxf(amt * r, 1e-5f);
    if (tid == 0) g_fact[t] = 1.f / scale;
    float f = r * scale;
    char4 c;
    c.x = (signed char)(int)fminf(fmaxf(rintf(v.x * f), -128.f), 127.f);
    c.y = (signed char)(int)fminf(fmaxf(rintf(v.y * f), -128.f), 127.f);
    c.z = (signed char)(int)fminf(fmaxf(rintf(v.z * f), -128.f), 127.f);
    c.w = (signed char)(int)fminf(fmaxf(rintf(v.w * f), -128.f), 127.f);
    ((char4*)g_nact)[(size_t)t * (ED / 4) + tid] = c;
}

// ---------------- LayerNorm + RMSNorm + activation quant ----------------
__global__ void ln_quant(const float* __restrict__ g, const float* __restrict__ bb) {
    int t = blockIdx.x, tid = threadIdx.x;
    const float4* xr = (const float4*)(g_x + (size_t)t * ED);
    float4 v = xr[tid];
    float s1 = v.x + v.y + v.z + v.w;
    float s2 = v.x * v.x + v.y * v.y + v.z * v.z + v.w * v.w;
    #pragma unroll
    for (int o = 16; o; o >>= 1) {
        s1 += __shfl_xor_sync(0xffffffffu, s1, o);
        s2 += __shfl_xor_sync(0xffffffffu, s2, o);
    }
    __shared__ float sa[8], sb[8];
    int w = tid >> 5, l = tid & 31;
    if (l == 0) { sa[w] = s1; sb[w] = s2; }
    __syncthreads();
    float s1t = 0.f, s2t = 0.f;
    #pragma unroll
    for (int i = 0; i < 8; i++) { s1t += sa[i]; s2t += sb[i]; }
    float mu = s1t * (1.f / ED);
    float var = fmaxf(s2t * (1.f / ED) - mu * mu, 0.f);
    float inv = rsqrtf(var + 1e-5f);
    float4 gg = ((const float4*)g)[tid];
    float4 bv = ((const float4*)bb)[tid];
    float4 ln;
    ln.x = (v.x - mu) * inv * gg.x + bv.x;
    ln.y = (v.y - mu) * inv * gg.y + bv.y;
    ln.z = (v.z - mu) * inv * gg.z + bv.z;
    ln.w = (v.w - mu) * inv * gg.w + bv.w;
    float ss = ln.x * ln.x + ln.y * ln.y + ln.z * ln.z + ln.w * ln.w;
    float am = fmaxf(fmaxf(fabsf(ln.x), fabsf(ln.y)), fmaxf(fabsf(ln.z), fabsf(ln.w)));
    #pragma unroll
    for (int o = 16; o; o >>= 1) {
        ss += __shfl_xor_sync(0xffffffffu, ss, o);
        am = fmaxf(am, __shfl_xor_sync(0xffffffffu, am, o));
    }
    __syncthreads();   // sa/sb reuse
    if (l == 0) { sa[w] = ss; sb[w] = am; }
    __syncthreads();
    float sst = 0.f, amt = 0.f;
    #pragma unroll
    for (int i = 0; i < 8; i++) { sst += sa[i]; amt = fmaxf(amt, sb[i]); }
    float r = 1.f / (sqrtf(sst * (1.f / ED) + 1e-6f) * 32.f);
    float scale = 127.f / fmaxf(amt * r, 1e-5f);
    if (tid == 0) g_fact[t] = 1.f / scale;
    float f = r * scale;
    char4 c;
    c.x = (signed char)(int)fminf(fmaxf(rintf(ln.x * f), -128.f), 127.f);
    c.y = (signed char)(int)fminf(fmaxf(rintf(ln.y * f), -128.f), 127.f);
    c.z = (signed char)(int)fminf(fmaxf(rintf(ln.z * f), -128.f), 127.f);
    c.w = (signed char)(int)fminf(fmaxf(rintf(ln.w * f), -128.f), 127.f);
    ((char4*)g_nact)[(size_t)t * (ED / 4) + tid] = c;
}

// ---------------- exact int8 GEMM via dp4a: C = scale * (A·Bᵀ) + bias ----------------
__global__ void __launch_bounds__(256) gemm_i8(int mid, const float* __restrict__ bias,
                                               int N, float* __restrict__ Cext) {
    const int* A  = (const int*)g_nact;
    const int* Bm = (const int*)sel_sign(mid);
    float* C = (mid == 0) ? g_q : (mid == 1) ? g_k : (mid == 2) ? g_v : Cext;
    __shared__ int As[64][33];
    __shared__ int Bs[64][33];
    int tid = threadIdx.x, tx = tid & 15, ty = tid >> 4;
    int bm = blockIdx.y, bn = blockIdx.x;
    int acc[4][4] = {{0}};
    for (int kt = 0; kt < 8; kt++) {
        #pragma unroll
        for (int u = 0; u < 2; u++) {
            int idx = tid + u * 256;
            int row = idx >> 3, c4 = (idx & 7) << 2;
            int4 a = *(const int4*)&A[(size_t)(bm * 64 + row) * KI + kt * 32 + c4];
            As[row][c4 + 0] = a.x; As[row][c4 + 1] = a.y; As[row][c4 + 2] = a.z; As[row][c4 + 3] = a.w;
            int4 b = *(const int4*)&Bm[(size_t)(bn * 64 + row) * KI + kt * 32 + c4];
            Bs[row][c4 + 0] = b.x; Bs[row][c4 + 1] = b.y; Bs[row][c4 + 2] = b.z; Bs[row][c4 + 3] = b.w;
        }
        __syncthreads();
        #pragma unroll
        for (int kk = 0; kk < 32; kk++) {
            int a0 = As[ty * 4 + 0][kk], a1 = As[ty * 4 + 1][kk];
            int a2 = As[ty * 4 + 2][kk], a3 = As[ty * 4 + 3][kk];
            int b0 = Bs[tx][kk], b1 = Bs[tx + 16][kk], b2 = Bs[tx + 32][kk], b3 = Bs[tx + 48][kk];
            acc[0][0] = __dp4a(a0, b0, acc[0][0]); acc[0][1] = __dp4a(a0, b1, acc[0][1]);
            acc[0][2] = __dp4a(a0, b2, acc[0][2]); acc[0][3] = __dp4a(a0, b3, acc[0][3]);
            acc[1][0] = __dp4a(a1, b0, acc[1][0]); acc[1][1] = __dp4a(a1, b1, acc[1][1]);
            acc[1][2] = __dp4a(a1, b2, acc[1][2]); acc[1][3] = __dp4a(a1, b3, acc[1][3]);
            acc[2][0] = __dp4a(a2, b0, acc[2][0]); acc[2][1] = __dp4a(a2, b1, acc[2][1]);
            acc[2][2] = __dp4a(a2, b2, acc[2][2]); acc[2][3] = __dp4a(a2, b3, acc[2][3]);
            acc[3][0] = __dp4a(a3, b0, acc[3][0]); acc[3][1] = __dp4a(a3, b1, acc[3][1]);
            acc[3][2] = __dp4a(a3, b2, acc[3][2]); acc[3][3] = __dp4a(a3, b3, acc[3][3]);
        }
        __syncthreads();
    }
    float alpha = g_alpha[mid];
    #pragma unroll
    for (int i = 0; i < 4; i++) {
        int row = bm * 64 + ty * 4 + i;
        float sf = alpha * g_fact[row];
        #pragma unroll
        for (int j = 0; j < 4; j++) {
            int col = bn * 64 + tx + 16 * j;
            C[(size_t)row * N + col] = sf * (float)acc[i][j] + bias[col];
        }
    }
}

// ---------------- fp32 flash attention (GQA, non-causal) ----------------
#define AP 132
__global__ void __launch_bounds__(256) attn_fp32() {
    extern __shared__ float smf[];
    float* Qs = smf;
    float* Ks = Qs + 64 * AP;
    float* Vs = Ks + 64 * AP;
    float* Ps = Vs + 64 * AP;   // pitch 65
    int tid = threadIdx.x, tx = tid & 15, ty = tid >> 4;
    int qt = blockIdx.x, bh = blockIdx.y;
    int b = bh >> 3, h = bh & 7, kvh = h >> 2;
    const float* qb = g_q + (size_t)b * SEQ * ED + (size_t)h * HD;
    const float* kb = g_k + (size_t)b * SEQ * KVD + (size_t)kvh * HD;
    const float* vb = g_v + (size_t)b * SEQ * KVD + (size_t)kvh * HD;
    const float qsc = 0.08838834764831845f;  // 1/sqrt(128)
    #pragma unroll
    for (int u = 0; u < 8; u++) {
        int idx = tid + u * 256, row = idx >> 5, d4 = (idx & 31) << 2;
        float4 q = *(const float4*)&qb[(size_t)(qt * 64 + row) * ED + d4];
        q.x *= qsc; q.y *= qsc; q.z *= qsc; q.w *= qsc;
        *(float4*)&Qs[row * AP + d4] = q;
    }
    float m_[4], l_[4], acc[4][8];
    #pragma unroll
    for (int i = 0; i < 4; i++) {
        m_[i] = -1e30f; l_[i] = 0.f;
        #pragma unroll
        for (int d = 0; d < 8; d++) acc[i][d] = 0.f;
    }
    for (int kt = 0; kt < 32; kt++) {
        __syncthreads();
        #pragma unroll
        for (int u = 0; u < 8; u++) {
            int idx = tid + u * 256, row = idx >> 5, d4 = (idx & 31) << 2;
            *(float4*)&Ks[row * AP + d4] = *(const float4*)&kb[(size_t)(kt * 64 + row) * KVD + d4];
            *(float4*)&Vs[row * AP + d4] = *(const float4*)&vb[(size_t)(kt * 64 + row) * KVD + d4];
        }
        __syncthreads();
        float s[4][4] = {{0.f}};
        #pragma unroll 4
        for (int d4 = 0; d4 < 32; d4++) {
            int d = d4 << 2;
            float4 q0 = *(float4*)&Qs[(ty * 4 + 0) * AP + d];
            float4 q1 = *(float4*)&Qs[(ty * 4 + 1) * AP + d];
            float4 q2 = *(float4*)&Qs[(ty * 4 + 2) * AP + d];
            float4 q3 = *(float4*)&Qs[(ty * 4 + 3) * AP + d];
            float4 k0 = *(float4*)&Ks[(tx     ) * AP + d];
            float4 k1 = *(float4*)&Ks[(tx + 16) * AP + d];
            float4 k2 = *(float4*)&Ks[(tx + 32) * AP + d];
            float4 k3 = *(float4*)&Ks[(tx + 48) * AP + d];
            #define DOTACC(I,J,QV,KV) s[I][J] += QV.x*KV.x + QV.y*KV.y + QV.z*KV.z + QV.w*KV.w;
            DOTACC(0,0,q0,k0) DOTACC(0,1,q0,k1) DOTACC(0,2,q0,k2) DOTACC(0,3,q0,k3)
            DOTACC(1,0,q1,k0) DOTACC(1,1,q1,k1) DOTACC(1,2,q1,k2) DOTACC(1,3,q1,k3)
            DOTACC(2,0,q2,k0) DOTACC(2,1,q2,k1) DOTACC(2,2,q2,k2) DOTACC(2,3,q2,k3)
            DOTACC(3,0,q3,k0) DOTACC(3,1,q3,k1) DOTACC(3,2,q3,k2) DOTACC(3,3,q3,k3)
            #undef DOTACC
        }
        #pragma unroll
        for (int i = 0; i < 4; i++) {
            float rm = fmaxf(fmaxf(s[i][0], s[i][1]), fmaxf(s[i][2], s[i][3]));
            #pragma unroll
            for (int o = 8; o; o >>= 1) rm = fmaxf(rm, __shfl_xor_sync(0xffffffffu, rm, o));
            float mn = fmaxf(m_[i], rm);
            float corr = __expf(m_[i] - mn);
            float p0 = __expf(s[i][0] - mn), p1 = __expf(s[i][1] - mn);
            float p2 = __expf(s[i][2] - mn), p3 = __expf(s[i][3] - mn);
            float rs = p0 + p1 + p2 + p3;
            #pragma unroll
            for (int o = 8; o; o >>= 1) rs += __shfl_xor_sync(0xffffffffu, rs, o);
            l_[i] = l_[i] * corr + rs;
            m_[i] = mn;
            #pragma unroll
            for (int d = 0; d < 8; d++) acc[i][d] *= corr;
            int rp = (ty * 4 + i) * 65;
            Ps[rp + tx] = p0; Ps[rp + tx + 16] = p1; Ps[rp + tx + 32] = p2; Ps[rp + tx + 48] = p3;
        }
        __syncthreads();
        #pragma unroll 4
        for (int c = 0; c < 64; c++) {
            float p0 = Ps[(ty * 4 + 0) * 65 + c];
            float p1 = Ps[(ty * 4 + 1) * 65 + c];
            float p2 = Ps[(ty * 4 + 2) * 65 + c];
            float p3 = Ps[(ty * 4 + 3) * 65 + c];
            float4 va = *(float4*)&Vs[c * AP + tx * 8];
            float4 vb4 = *(float4*)&Vs[c * AP + tx * 8 + 4];
            acc[0][0] += p0 * va.x; acc[0][1] += p0 * va.y; acc[0][2] += p0 * va.z; acc[0][3] += p0 * va.w;
            acc[0][4] += p0 * vb4.x; acc[0][5] += p0 * vb4.y; acc[0][6] += p0 * vb4.z; acc[0][7] += p0 * vb4.w;
            acc[1][0] += p1 * va.x; acc[1][1] += p1 * va.y; acc[1][2] += p1 * va.z; acc[1][3] += p1 * va.w;
            acc[1][4] += p1 * vb4.x; acc[1][5] += p1 * vb4.y; acc[1][6] += p1 * vb4.z; acc[1][7] += p1 * vb4.w;
            acc[2][0] += p2 * va.x; acc[2][1] += p2 * va.y; acc[2][2] += p2 * va.z; acc[2][3] += p2 * va.w;
            acc[2][4] += p2 * vb4.x; acc[2][5] += p2 * vb4.y; acc[2][6] += p2 * vb4.z; acc[2][7] += p2 * vb4.w;
            acc[3][0] += p3 * va.x; acc[3][1] += p3 * va.y; acc[3][2] += p3 * va.z; acc[3][3] += p3 * va.w;
            acc[3][4] += p3 * vb4.x; acc[3][5] += p3 * vb4.y; acc[3][6] += p3 * vb4.z; acc[3][7] += p3 * vb4.w;
        }
    }
    #pragma unroll
    for (int i = 0; i < 4; i++) {
        float inv = 1.f / l_[i];
        int row = qt * 64 + ty * 4 + i;
        float* xo = g_x + ((size_t)b * SEQ + row) * ED + h * HD + tx * 8;
        float4 o1 = make_float4(acc[i][0] * inv, acc[i][1] * inv, acc[i][2] * inv, acc[i][3] * inv);
        float4 o2 = make_float4(acc[i][4] * inv, acc[i][5] * inv, acc[i][6] * inv, acc[i][7] * inv);
        *(float4*)xo = o1;
        *(float4*)(xo + 4) = o2;
    }
}

// ---------------- launch ----------------
extern "C" void kernel_launch(void* const* d_in, const int* in_sizes, int n_in,
                              void* d_out, int out_size) {
    const float* query = (const float*)d_in[0];
    const float* key   = (const float*)d_in[1];
    const float* value = (const float*)d_in[2];
    const float* q_w   = (const float*)d_in[3];
    const float* q_b   = (const float*)d_in[4];
    const float* k_w   = (const float*)d_in[5];
    const float* k_b   = (const float*)d_in[6];
    const float* v_w   = (const float*)d_in[7];
    const float* v_b   = (const float*)d_in[8];
    const float* ln_g  = (const float*)d_in[9];
    const float* ln_b  = (const float*)d_in[10];
    const float* out_w = (const float*)d_in[11];
    const float* out_b = (const float*)d_in[12];

    // weight prep (cheap; recomputed every call for determinism)
    absmean_partial<<<128, 256>>>(q_w,   ED * ED,  0);
    absmean_partial<<<128, 256>>>(k_w,   KVD * ED, 1);
    absmean_partial<<<128, 256>>>(v_w,   KVD * ED, 2);
    absmean_partial<<<128, 256>>>(out_w, ED * ED,  3);
    absmean_final<<<1, 128>>>();
    sign_pack<<<ED * ED / 4 / 256, 256>>>(q_w,   0, ED * ED / 4);
    sign_pack<<<KVD * ED / 4 / 256, 256>>>(k_w,  1, KVD * ED / 4);
    sign_pack<<<KVD * ED / 4 / 256, 256>>>(v_w,  2, KVD * ED / 4);
    sign_pack<<<ED * ED / 4 / 256, 256>>>(out_w, 3, ED * ED / 4);

    // projections (exact int8 path)
    quant_rms<<<NTOK, 256>>>(query);
    gemm_i8<<<dim3(ED / 64, NTOK / 64), 256>>>(0, q_b, ED, nullptr);
    quant_rms<<<NTOK, 256>>>(key);
    gemm_i8<<<dim3(KVD / 64, NTOK / 64), 256>>>(1, k_b, KVD, nullptr);
    quant_rms<<<NTOK, 256>>>(value);
    gemm_i8<<<dim3(KVD / 64, NTOK / 64), 256>>>(2, v_b, KVD, nullptr);

    // attention
    cudaFuncSetAttribute(attn_fp32, cudaFuncAttributeMaxDynamicSharedMemorySize, 118016);
    attn_fp32<<<dim3(SEQ / 64, 16), 256, 118016>>>();

    // layernorm + final bitlinear
    ln_quant<<<NTOK, 256>>>(ln_g, ln_b);
    gemm_i8<<<dim3(ED / 64, NTOK / 64), 256>>>(3, out_b, ED, (float*)d_out);
}

// round 2
// speedup vs baseline: 1.1378x; 1.1378x over previous
#include <cuda_runtime.h>
#include <math.h>

#define SEQ   2048
#define NTOK  4096
#define ED    1024
#define KVD   256
#define HD    128
#define KI    256   // ints per activation row (ED/4)

// ---------------- device scratch (no allocations allowed) ----------------
__device__ float g_alpha[4];
__device__ float g_part[4][256];
__device__ signed char g_sq[ED*ED];
__device__ signed char g_sk[KVD*ED];
__device__ signed char g_sv[KVD*ED];
__device__ signed char g_so[ED*ED];
__device__ signed char g_nact[NTOK*ED];
__device__ float g_fact[NTOK];
__device__ float g_q[NTOK*ED];
__device__ float g_k[NTOK*KVD];
__device__ float g_v[NTOK*KVD];
__device__ float g_x[NTOK*ED];

__device__ __forceinline__ signed char* sel_sign(int m) {
    return m == 0 ? g_sq : m == 1 ? g_sk : m == 2 ? g_sv : g_so;
}

// ---------------- packed f32x2 helpers (sm_103a) ----------------
#define FMA2(D,A,B) asm("fma.rn.f32x2 %0, %1, %2, %0;" : "+l"(D) : "l"(A), "l"(B))
#define MUL2(D,A,B) asm("mul.rn.f32x2 %0, %1, %2;" : "=l"(D) : "l"(A), "l"(B))
__device__ __forceinline__ unsigned long long pk2(float a, float b) {
    unsigned long long r;
    asm("mov.b64 %0, {%1, %2};" : "=l"(r) : "r"(__float_as_uint(a)), "r"(__float_as_uint(b)));
    return r;
}
__device__ __forceinline__ float lo2(unsigned long long u) { return __uint_as_float((unsigned)u); }
__device__ __forceinline__ float hi2(unsigned long long u) { return __uint_as_float((unsigned)(u >> 32)); }

// ---------------- fused weight prep: sign pack + |w| partial sums ----------------
__global__ void prep_w(const float4* __restrict__ w, int n4, int mid) {
    __shared__ float sh[256];
    float s = 0.f;
    char4* dst = (char4*)sel_sign(mid);
    for (int i = blockIdx.x * 256 + threadIdx.x; i < n4; i += 256 * 256) {
        float4 v = w[i];
        s += fabsf(v.x) + fabsf(v.y) + fabsf(v.z) + fabsf(v.w);
        char4 c;
        c.x = (signed char)((v.x > 0.f) - (v.x < 0.f));
        c.y = (signed char)((v.y > 0.f) - (v.y < 0.f));
        c.z = (signed char)((v.z > 0.f) - (v.z < 0.f));
        c.w = (signed char)((v.w > 0.f) - (v.w < 0.f));
        dst[i] = c;
    }
    sh[threadIdx.x] = s;
    __syncthreads();
    for (int o = 128; o > 0; o >>= 1) {
        if (threadIdx.x < o) sh[threadIdx.x] += sh[threadIdx.x + o];
        __syncthreads();
    }
    if (threadIdx.x == 0) g_part[mid][blockIdx.x] = sh[0];
}

__global__ void absmean_final() {
    int m = blockIdx.x;
    __shared__ float sh[256];
    sh[threadIdx.x] = g_part[m][threadIdx.x];
    __syncthreads();
    for (int o = 128; o > 0; o >>= 1) {
        if (threadIdx.x < o) sh[threadIdx.x] += sh[threadIdx.x + o];
        __syncthreads();
    }
    if (threadIdx.x == 0) {
        float n = (m == 1 || m == 2) ? (float)(KVD * ED) : (float)(ED * ED);
        g_alpha[m] = sh[0] / n;
    }
}

// ---------------- RMSNorm + activation quant (per token) ----------------
__global__ void quant_rms(const float* __restrict__ x) {
    int t = blockIdx.x, tid = threadIdx.x;
    const float4* xr = (const float4*)(x + (size_t)t * ED);
    float4 v = xr[tid];
    float ss = v.x * v.x + v.y * v.y + v.z * v.z + v.w * v.w;
    float am = fmaxf(fmaxf(fabsf(v.x), fabsf(v.y)), fmaxf(fabsf(v.z), fabsf(v.w)));
    #pragma unroll
    for (int o = 16; o; o >>= 1) {
        ss += __shfl_xor_sync(0xffffffffu, ss, o);
        am = fmaxf(am, __shfl_xor_sync(0xffffffffu, am, o));
    }
    __shared__ float sa[8], sb[8];
    int w = tid >> 5, l = tid & 31;
    if (l == 0) { sa[w] = ss; sb[w] = am; }
    __syncthreads();
    float sst = 0.f, amt = 0.f;
    #pragma unroll
    for (int i = 0; i < 8; i++) { sst += sa[i]; amt = fmaxf(amt, sb[i]); }
    float r = 1.f / (sqrtf(sst * (1.f / ED) + 1e-6f) * 32.f);
    float scale = 127.f / fmaxf(amt * r, 1e-5f);
    if (tid == 0) g_fact[t] = 1.f / scale;
    float f = r * scale;
    char4 c;
    c.x = (signed char)(int)fminf(fmaxf(rintf(v.x * f), -128.f), 127.f);
    c.y = (signed char)(int)fminf(fmaxf(rintf(v.y * f), -128.f), 127.f);
    c.z = (signed char)(int)fminf(fmaxf(rintf(v.z * f), -128.f), 127.f);
    c.w = (signed char)(int)fminf(fmaxf(rintf(v.w * f), -128.f), 127.f);
    ((char4*)g_nact)[(size_t)t * (ED / 4) + tid] = c;
}

// ---------------- LayerNorm + RMSNorm + activation quant ----------------
__global__ void ln_quant(const float* __restrict__ g, const float* __restrict__ bb) {
    int t = blockIdx.x, tid = threadIdx.x;
    const float4* xr = (const float4*)(g_x + (size_t)t * ED);
    float4 v = xr[tid];
    float s1 = v.x + v.y + v.z + v.w;
    float s2 = v.x * v.x + v.y * v.y + v.z * v.z + v.w * v.w;
    #pragma unroll
    for (int o = 16; o; o >>= 1) {
        s1 += __shfl_xor_sync(0xffffffffu, s1, o);
        s2 += __shfl_xor_sync(0xffffffffu, s2, o);
    }
    __shared__ float sa[8], sb[8];
    int w = tid >> 5, l = tid & 31;
    if (l == 0) { sa[w] = s1; sb[w] = s2; }
    __syncthreads();
    float s1t = 0.f, s2t = 0.f;
    #pragma unroll
    for (int i = 0; i < 8; i++) { s1t += sa[i]; s2t += sb[i]; }
    float mu = s1t * (1.f / ED);
    float var = fmaxf(s2t * (1.f / ED) - mu * mu, 0.f);
    float inv = rsqrtf(var + 1e-5f);
    float4 gg = ((const float4*)g)[tid];
    float4 bv = ((const float4*)bb)[tid];
    float4 ln;
    ln.x = (v.x - mu) * inv * gg.x + bv.x;
    ln.y = (v.y - mu) * inv * gg.y + bv.y;
    ln.z = (v.z - mu) * inv * gg.z + bv.z;
    ln.w = (v.w - mu) * inv * gg.w + bv.w;
    float ss = ln.x * ln.x + ln.y * ln.y + ln.z * ln.z + ln.w * ln.w;
    float am = fmaxf(fmaxf(fabsf(ln.x), fabsf(ln.y)), fmaxf(fabsf(ln.z), fabsf(ln.w)));
    #pragma unroll
    for (int o = 16; o; o >>= 1) {
        ss += __shfl_xor_sync(0xffffffffu, ss, o);
        am = fmaxf(am, __shfl_xor_sync(0xffffffffu, am, o));
    }
    __syncthreads();   // sa/sb reuse
    if (l == 0) { sa[w] = ss; sb[w] = am; }
    __syncthreads();
    float sst = 0.f, amt = 0.f;
    #pragma unroll
    for (int i = 0; i < 8; i++) { sst += sa[i]; amt = fmaxf(amt, sb[i]); }
    float r = 1.f / (sqrtf(sst * (1.f / ED) + 1e-6f) * 32.f);
    float scale = 127.f / fmaxf(amt * r, 1e-5f);
    if (tid == 0) g_fact[t] = 1.f / scale;
    float f = r * scale;
    char4 c;
    c.x = (signed char)(int)fminf(fmaxf(rintf(ln.x * f), -128.f), 127.f);
    c.y = (signed char)(int)fminf(fmaxf(rintf(ln.y * f), -128.f), 127.f);
    c.z = (signed char)(int)fminf(fmaxf(rintf(ln.z * f), -128.f), 127.f);
    c.w = (signed char)(int)fminf(fmaxf(rintf(ln.w * f), -128.f), 127.f);
    ((char4*)g_nact)[(size_t)t * (ED / 4) + tid] = c;
}

// ---------------- exact int8 GEMM via dp4a: C = scale * (A·Bᵀ) + bias ----------------
__global__ void __launch_bounds__(256) gemm_i8(int mid, const float* __restrict__ bias,
                                               int N, float* __restrict__ Cext) {
    const int* A  = (const int*)g_nact;
    const int* Bm = (const int*)sel_sign(mid);
    float* C = (mid == 0) ? g_q : (mid == 1) ? g_k : (mid == 2) ? g_v : Cext;
    __shared__ int As[64][33];
    __shared__ int Bs[64][33];
    int tid = threadIdx.x, tx = tid & 15, ty = tid >> 4;
    int bm = blockIdx.y, bn = blockIdx.x;
    int acc[4][4] = {{0}};
    for (int kt = 0; kt < 8; kt++) {
        #pragma unroll
        for (int u = 0; u < 2; u++) {
            int idx = tid + u * 256;
            int row = idx >> 3, c4 = (idx & 7) << 2;
            int4 a = *(const int4*)&A[(size_t)(bm * 64 + row) * KI + kt * 32 + c4];
            As[row][c4 + 0] = a.x; As[row][c4 + 1] = a.y; As[row][c4 + 2] = a.z; As[row][c4 + 3] = a.w;
            int4 b = *(const int4*)&Bm[(size_t)(bn * 64 + row) * KI + kt * 32 + c4];
            Bs[row][c4 + 0] = b.x; Bs[row][c4 + 1] = b.y; Bs[row][c4 + 2] = b.z; Bs[row][c4 + 3] = b.w;
        }
        __syncthreads();
        #pragma unroll
        for (int kk = 0; kk < 32; kk++) {
            int a0 = As[ty * 4 + 0][kk], a1 = As[ty * 4 + 1][kk];
            int a2 = As[ty * 4 + 2][kk], a3 = As[ty * 4 + 3][kk];
            int b0 = Bs[tx][kk], b1 = Bs[tx + 16][kk], b2 = Bs[tx + 32][kk], b3 = Bs[tx + 48][kk];
            acc[0][0] = __dp4a(a0, b0, acc[0][0]); acc[0][1] = __dp4a(a0, b1, acc[0][1]);
            acc[0][2] = __dp4a(a0, b2, acc[0][2]); acc[0][3] = __dp4a(a0, b3, acc[0][3]);
            acc[1][0] = __dp4a(a1, b0, acc[1][0]); acc[1][1] = __dp4a(a1, b1, acc[1][1]);
            acc[1][2] = __dp4a(a1, b2, acc[1][2]); acc[1][3] = __dp4a(a1, b3, acc[1][3]);
            acc[2][0] = __dp4a(a2, b0, acc[2][0]); acc[2][1] = __dp4a(a2, b1, acc[2][1]);
            acc[2][2] = __dp4a(a2, b2, acc[2][2]); acc[2][3] = __dp4a(a2, b3, acc[2][3]);
            acc[3][0] = __dp4a(a3, b0, acc[3][0]); acc[3][1] = __dp4a(a3, b1, acc[3][1]);
            acc[3][2] = __dp4a(a3, b2, acc[3][2]); acc[3][3] = __dp4a(a3, b3, acc[3][3]);
        }
        __syncthreads();
    }
    float alpha = g_alpha[mid];
    #pragma unroll
    for (int i = 0; i < 4; i++) {
        int row = bm * 64 + ty * 4 + i;
        float sf = alpha * g_fact[row];
        #pragma unroll
        for (int j = 0; j < 4; j++) {
            int col = bn * 64 + tx + 16 * j;
            C[(size_t)row * N + col] = sf * (float)acc[i][j] + bias[col];
        }
    }
}

// ---------------- fp32 flash attention (GQA, non-causal), f32x2 packed math ----------------
#define AP 132
#define PP 68
__global__ void __launch_bounds__(256) attn_fp32() {
    extern __shared__ float smf[];
    float* Qs = smf;
    float* Ks = Qs + 64 * AP;
    float* Vs = Ks + 64 * AP;
    float* Ps = Vs + 64 * AP;   // pitch PP
    int tid = threadIdx.x, tx = tid & 15, ty = tid >> 4;
    int qt = blockIdx.x, bh = blockIdx.y;
    int b = bh >> 3, h = bh & 7, kvh = h >> 2;
    const float* qb = g_q + (size_t)b * SEQ * ED + (size_t)h * HD;
    const float* kb = g_k + (size_t)b * SEQ * KVD + (size_t)kvh * HD;
    const float* vb = g_v + (size_t)b * SEQ * KVD + (size_t)kvh * HD;
    const float qsc = 0.08838834764831845f;  // 1/sqrt(128)
    #pragma unroll
    for (int u = 0; u < 8; u++) {
        int idx = tid + u * 256, row = idx >> 5, d4 = (idx & 31) << 2;
        float4 q = *(const float4*)&qb[(size_t)(qt * 64 + row) * ED + d4];
        q.x *= qsc; q.y *= qsc; q.z *= qsc; q.w *= qsc;
        *(float4*)&Qs[row * AP + d4] = q;
    }
    float m_[4], l_[4];
    unsigned long long acc2[4][4];   // per row: 4 packed d-pairs (8 d's)
    #pragma unroll
    for (int i = 0; i < 4; i++) {
        m_[i] = -1e30f; l_[i] = 0.f;
        #pragma unroll
        for (int p = 0; p < 4; p++) acc2[i][p] = 0ULL;
    }
    for (int kt = 0; kt < 32; kt++) {
        __syncthreads();
        #pragma unroll
        for (int u = 0; u < 8; u++) {
            int idx = tid + u * 256, row = idx >> 5, d4 = (idx & 31) << 2;
            *(float4*)&Ks[row * AP + d4] = *(const float4*)&kb[(size_t)(kt * 64 + row) * KVD + d4];
            *(float4*)&Vs[row * AP + d4] = *(const float4*)&vb[(size_t)(kt * 64 + row) * KVD + d4];
        }
        __syncthreads();
        // ---- scores: packed over d ----
        unsigned long long s2[4][4];
        #pragma unroll
        for (int i = 0; i < 4; i++)
            #pragma unroll
            for (int j = 0; j < 4; j++) s2[i][j] = 0ULL;
        #pragma unroll 4
        for (int d = 0; d < 128; d += 4) {
            ulonglong2 q0 = *(const ulonglong2*)&Qs[(ty * 4 + 0) * AP + d];
            ulonglong2 q1 = *(const ulonglong2*)&Qs[(ty * 4 + 1) * AP + d];
            ulonglong2 q2 = *(const ulonglong2*)&Qs[(ty * 4 + 2) * AP + d];
            ulonglong2 q3 = *(const ulonglong2*)&Qs[(ty * 4 + 3) * AP + d];
            ulonglong2 k0 = *(const ulonglong2*)&Ks[(tx     ) * AP + d];
            ulonglong2 k1 = *(const ulonglong2*)&Ks[(tx + 16) * AP + d];
            ulonglong2 k2 = *(const ulonglong2*)&Ks[(tx + 32) * AP + d];
            ulonglong2 k3 = *(const ulonglong2*)&Ks[(tx + 48) * AP + d];
            FMA2(s2[0][0], q0.x, k0.x); FMA2(s2[0][0], q0.y, k0.y);
            FMA2(s2[0][1], q0.x, k1.x); FMA2(s2[0][1], q0.y, k1.y);
            FMA2(s2[0][2], q0.x, k2.x); FMA2(s2[0][2], q0.y, k2.y);
            FMA2(s2[0][3], q0.x, k3.x); FMA2(s2[0][3], q0.y, k3.y);
            FMA2(s2[1][0], q1.x, k0.x); FMA2(s2[1][0], q1.y, k0.y);
            FMA2(s2[1][1], q1.x, k1.x); FMA2(s2[1][1], q1.y, k1.y);
            FMA2(s2[1][2], q1.x, k2.x); FMA2(s2[1][2], q1.y, k2.y);
            FMA2(s2[1][3], q1.x, k3.x); FMA2(s2[1][3], q1.y, k3.y);
            FMA2(s2[2][0], q2.x, k0.x); FMA2(s2[2][0], q2.y, k0.y);
            FMA2(s2[2][1], q2.x, k1.x); FMA2(s2[2][1], q2.y, k1.y);
            FMA2(s2[2][2], q2.x, k2.x); FMA2(s2[2][2], q2.y, k2.y);
            FMA2(s2[2][3], q2.x, k3.x); FMA2(s2[2][3], q2.y, k3.y);
            FMA2(s2[3][0], q3.x, k0.x); FMA2(s2[3][0], q3.y, k0.y);
            FMA2(s2[3][1], q3.x, k1.x); FMA2(s2[3][1], q3.y, k1.y);
            FMA2(s2[3][2], q3.x, k2.x); FMA2(s2[3][2], q3.y, k2.y);
            FMA2(s2[3][3], q3.x, k3.x); FMA2(s2[3][3], q3.y, k3.y);
        }
        float s[4][4];
        #pragma unroll
        for (int i = 0; i < 4; i++)
            #pragma unroll
            for (int j = 0; j < 4; j++) s[i][j] = lo2(s2[i][j]) + hi2(s2[i][j]);
        // ---- online softmax ----
        #pragma unroll
        for (int i = 0; i < 4; i++) {
            float rm = fmaxf(fmaxf(s[i][0], s[i][1]), fmaxf(s[i][2], s[i][3]));
            #pragma unroll
            for (int o = 8; o; o >>= 1) rm = fmaxf(rm, __shfl_xor_sync(0xffffffffu, rm, o));
            float mn = fmaxf(m_[i], rm);
            float corr = __expf(m_[i] - mn);
            float p0 = __expf(s[i][0] - mn), p1 = __expf(s[i][1] - mn);
            float p2 = __expf(s[i][2] - mn), p3 = __expf(s[i][3] - mn);
            float rs = p0 + p1 + p2 + p3;
            #pragma unroll
            for (int o = 8; o; o >>= 1) rs += __shfl_xor_sync(0xffffffffu, rs, o);
            l_[i] = l_[i] * corr + rs;
            m_[i] = mn;
            unsigned long long corr2 = pk2(corr, corr);
            #pragma unroll
            for (int p = 0; p < 4; p++) MUL2(acc2[i][p], acc2[i][p], corr2);
            int rp = (ty * 4 + i) * PP;
            Ps[rp + tx] = p0; Ps[rp + tx + 16] = p1; Ps[rp + tx + 32] = p2; Ps[rp + tx + 48] = p3;
        }
        __syncthreads();
        // ---- PV: packed over d, p as float4 over c ----
        #pragma unroll 2
        for (int c = 0; c < 64; c += 4) {
            float4 pr0 = *(const float4*)&Ps[(ty * 4 + 0) * PP + c];
            float4 pr1 = *(const float4*)&Ps[(ty * 4 + 1) * PP + c];
            float4 pr2 = *(const float4*)&Ps[(ty * 4 + 2) * PP + c];
            float4 pr3 = *(const float4*)&Ps[(ty * 4 + 3) * PP + c];
            #define PVC(CI, P0, P1, P2, P3) { \
                ulonglong2 va = *(const ulonglong2*)&Vs[(c + CI) * AP + tx * 8]; \
                ulonglong2 vb2 = *(const ulonglong2*)&Vs[(c + CI) * AP + tx * 8 + 4]; \
                unsigned long long pp; \
                pp = pk2(P0, P0); FMA2(acc2[0][0], pp, va.x); FMA2(acc2[0][1], pp, va.y); \
                                  FMA2(acc2[0][2], pp, vb2.x); FMA2(acc2[0][3], pp, vb2.y); \
                pp = pk2(P1, P1); FMA2(acc2[1][0], pp, va.x); FMA2(acc2[1][1], pp, va.y); \
                                  FMA2(acc2[1][2], pp, vb2.x); FMA2(acc2[1][3], pp, vb2.y); \
                pp = pk2(P2, P2); FMA2(acc2[2][0], pp, va.x); FMA2(acc2[2][1], pp, va.y); \
                                  FMA2(acc2[2][2], pp, vb2.x); FMA2(acc2[2][3], pp, vb2.y); \
                pp = pk2(P3, P3); FMA2(acc2[3][0], pp, va.x); FMA2(acc2[3][1], pp, va.y); \
                                  FMA2(acc2[3][2], pp, vb2.x); FMA2(acc2[3][3], pp, vb2.y); }
            PVC(0, pr0.x, pr1.x, pr2.x, pr3.x)
            PVC(1, pr0.y, pr1.y, pr2.y, pr3.y)
            PVC(2, pr0.z, pr1.z, pr2.z, pr3.z)
            PVC(3, pr0.w, pr1.w, pr2.w, pr3.w)
            #undef PVC
        }
    }
    #pragma unroll
    for (int i = 0; i < 4; i++) {
        float inv = 1.f / l_[i];
        int row = qt * 64 + ty * 4 + i;
        float* xo = g_x + ((size_t)b * SEQ + row) * ED + h * HD + tx * 8;
        float4 o1 = make_float4(lo2(acc2[i][0]) * inv, hi2(acc2[i][0]) * inv,
                                lo2(acc2[i][1]) * inv, hi2(acc2[i][1]) * inv);
        float4 o2 = make_float4(lo2(acc2[i][2]) * inv, hi2(acc2[i][2]) * inv,
                                lo2(acc2[i][3]) * inv, hi2(acc2[i][3]) * inv);
        *(float4*)xo = o1;
        *(float4*)(xo + 4) = o2;
    }
}

// ---------------- launch ----------------
extern "C" void kernel_launch(void* const* d_in, const int* in_sizes, int n_in,
                              void* d_out, int out_size) {
    const float* query = (const float*)d_in[0];
    const float* key   = (const float*)d_in[1];
    const float* value = (const float*)d_in[2];
    const float* q_w   = (const float*)d_in[3];
    const float* q_b   = (const float*)d_in[4];
    const float* k_w   = (const float*)d_in[5];
    const float* k_b   = (const float*)d_in[6];
    const float* v_w   = (const float*)d_in[7];
    const float* v_b   = (const float*)d_in[8];
    const float* ln_g  = (const float*)d_in[9];
    const float* ln_b  = (const float*)d_in[10];
    const float* out_w = (const float*)d_in[11];
    const float* out_b = (const float*)d_in[12];

    // fused weight prep: sign pack + |w| partial sums in one pass
    prep_w<<<256, 256>>>((const float4*)q_w,   ED * ED / 4,  0);
    prep_w<<<256, 256>>>((const float4*)k_w,   KVD * ED / 4, 1);
    prep_w<<<256, 256>>>((const float4*)v_w,   KVD * ED / 4, 2);
    prep_w<<<256, 256>>>((const float4*)out_w, ED * ED / 4,  3);
    absmean_final<<<4, 256>>>();

    // projections (exact int8 path)
    quant_rms<<<NTOK, 256>>>(query);
    gemm_i8<<<dim3(ED / 64, NTOK / 64), 256>>>(0, q_b, ED, nullptr);
    quant_rms<<<NTOK, 256>>>(key);
    gemm_i8<<<dim3(KVD / 64, NTOK / 64), 256>>>(1, k_b, KVD, nullptr);
    quant_rms<<<NTOK, 256>>>(value);
    gemm_i8<<<dim3(KVD / 64, NTOK / 64), 256>>>(2, v_b, KVD, nullptr);

    // attention (fp32-exact, f32x2 packed)
    cudaFuncSetAttribute(attn_fp32, cudaFuncAttributeMaxDynamicSharedMemorySize, 118784);
    attn_fp32<<<dim3(SEQ / 64, 16), 256, 118784>>>();

    // layernorm + final bitlinear
    ln_quant<<<NTOK, 256>>>(ln_g, ln_b);
    gemm_i8<<<dim3(ED / 64, NTOK / 64), 256>>>(3, out_b, ED, (float*)d_out);
}

// round 4
// speedup vs baseline: 1.2022x; 1.0566x over previous
#include <cuda_runtime.h>
#include <cuda_bf16.h>
#include <math.h>
#include <stdint.h>

#define SEQ   2048
#define NTOK  4096
#define ED    1024
#define KVD   256
#define HD    128

// ---------------- device scratch (no allocations allowed) ----------------
__device__ float g_alpha[4];
__device__ float g_part[4][256];
__device__ __nv_bfloat16 g_wq[ED*ED];
__device__ __nv_bfloat16 g_wk[KVD*ED];
__device__ __nv_bfloat16 g_wv[KVD*ED];
__device__ __nv_bfloat16 g_wo[ED*ED];
__device__ __nv_bfloat16 g_actbf[NTOK*ED];
__device__ float g_fact[NTOK];
__device__ float g_q[NTOK*ED];
__device__ float g_k[NTOK*KVD];
__device__ float g_v[NTOK*KVD];
__device__ float g_x[NTOK*ED];

__device__ __forceinline__ __nv_bfloat16* sel_w(int m) {
    return m == 0 ? g_wq : m == 1 ? g_wk : m == 2 ? g_wv : g_wo;
}

__device__ __forceinline__ uint32_t smem_u32(const void* p) {
    uint32_t a;
    asm("{ .reg .u64 t; cvta.to.shared.u64 t, %1; cvt.u32.u64 %0, t; }" : "=r"(a) : "l"(p));
    return a;
}
__device__ __forceinline__ unsigned pack_bf2(float a, float b) {
    return (unsigned)__bfloat16_as_ushort(__float2bfloat16_rn(a)) |
           ((unsigned)__bfloat16_as_ushort(__float2bfloat16_rn(b)) << 16);
}

#define LDSM4(R0,R1,R2,R3,ADDR) \
    asm volatile("ldmatrix.sync.aligned.m8n8.x4.shared.b16 {%0,%1,%2,%3}, [%4];" \
        : "=r"(R0), "=r"(R1), "=r"(R2), "=r"(R3) : "r"(ADDR))
#define MMA16816(C, A0,A1,A2,A3, B0,B1) \
    asm volatile("mma.sync.aligned.m16n8k16.row.col.f32.bf16.bf16.f32 " \
        "{%0,%1,%2,%3}, {%4,%5,%6,%7}, {%8,%9}, {%0,%1,%2,%3};" \
        : "+f"((C)[0]), "+f"((C)[1]), "+f"((C)[2]), "+f"((C)[3]) \
        : "r"(A0), "r"(A1), "r"(A2), "r"(A3), "r"(B0), "r"(B1))

// ---------------- packed f32x2 helpers (sm_103a) ----------------
#define FMA2(D,A,B) asm("fma.rn.f32x2 %0, %1, %2, %0;" : "+l"(D) : "l"(A), "l"(B))
#define MUL2(D,A,B) asm("mul.rn.f32x2 %0, %1, %2;" : "=l"(D) : "l"(A), "l"(B))
__device__ __forceinline__ unsigned long long pk2(float a, float b) {
    unsigned long long r;
    asm("mov.b64 %0, {%1, %2};" : "=l"(r) : "r"(__float_as_uint(a)), "r"(__float_as_uint(b)));
    return r;
}
__device__ __forceinline__ float lo2(unsigned long long u) { return __uint_as_float((unsigned)u); }
__device__ __forceinline__ float hi2(unsigned long long u) { return __uint_as_float((unsigned)(u >> 32)); }

// ---------------- fused weight prep: bf16 sign pack + |w| partial sums ----------------
__global__ void prep_w(const float4* __restrict__ w, int n4, int mid) {
    __shared__ float sh[256];
    float s = 0.f;
    uint2* dst = (uint2*)sel_w(mid);
    for (int i = blockIdx.x * 256 + threadIdx.x; i < n4; i += 256 * 256) {
        float4 v = w[i];
        s += fabsf(v.x) + fabsf(v.y) + fabsf(v.z) + fabsf(v.w);
        uint2 c;
        c.x = pack_bf2((float)((v.x > 0.f) - (v.x < 0.f)), (float)((v.y > 0.f) - (v.y < 0.f)));
        c.y = pack_bf2((float)((v.z > 0.f) - (v.z < 0.f)), (float)((v.w > 0.f) - (v.w < 0.f)));
        dst[i] = c;
    }
    sh[threadIdx.x] = s;
    __syncthreads();
    for (int o = 128; o > 0; o >>= 1) {
        if (threadIdx.x < o) sh[threadIdx.x] += sh[threadIdx.x + o];
        __syncthreads();
    }
    if (threadIdx.x == 0) g_part[mid][blockIdx.x] = sh[0];
}

__global__ void absmean_final() {
    int m = blockIdx.x;
    __shared__ float sh[256];
    sh[threadIdx.x] = g_part[m][threadIdx.x];
    __syncthreads();
    for (int o = 128; o > 0; o >>= 1) {
        if (threadIdx.x < o) sh[threadIdx.x] += sh[threadIdx.x + o];
        __syncthreads();
    }
    if (threadIdx.x == 0) {
        float n = (m == 1 || m == 2) ? (float)(KVD * ED) : (float)(ED * ED);
        g_alpha[m] = sh[0] / n;
    }
}

// ---------------- RMSNorm + activation quant (per token) -> bf16 ----------------
__global__ void quant_rms(const float* __restrict__ x) {
    int t = blockIdx.x, tid = threadIdx.x;
    const float4* xr = (const float4*)(x + (size_t)t * ED);
    float4 v = xr[tid];
    float ss = v.x * v.x + v.y * v.y + v.z * v.z + v.w * v.w;
    float am = fmaxf(fmaxf(fabsf(v.x), fabsf(v.y)), fmaxf(fabsf(v.z), fabsf(v.w)));
    #pragma unroll
    for (int o = 16; o; o >>= 1) {
        ss += __shfl_xor_sync(0xffffffffu, ss, o);
        am = fmaxf(am, __shfl_xor_sync(0xffffffffu, am, o));
    }
    __shared__ float sa[8], sb[8];
    int w = tid >> 5, l = tid & 31;
    if (l == 0) { sa[w] = ss; sb[w] = am; }
    __syncthreads();
    float sst = 0.f, amt = 0.f;
    #pragma unroll
    for (int i = 0; i < 8; i++) { sst += sa[i]; amt = fmaxf(amt, sb[i]); }
    float r = 1.f / (sqrtf(sst * (1.f / ED) + 1e-6f) * 32.f);
    float scale = 127.f / fmaxf(amt * r, 1e-5f);
    if (tid == 0) g_fact[t] = 1.f / scale;
    float f = r * scale;
    float qx = fminf(fmaxf(rintf(v.x * f), -128.f), 127.f);
    float qy = fminf(fmaxf(rintf(v.y * f), -128.f), 127.f);
    float qz = fminf(fmaxf(rintf(v.z * f), -128.f), 127.f);
    float qw = fminf(fmaxf(rintf(v.w * f), -128.f), 127.f);
    uint2 c; c.x = pack_bf2(qx, qy); c.y = pack_bf2(qz, qw);
    ((uint2*)g_actbf)[(size_t)t * (ED / 4) + tid] = c;
}

// ---------------- LayerNorm + RMSNorm + activation quant -> bf16 ----------------
__global__ void ln_quant(const float* __restrict__ g, const float* __restrict__ bb) {
    int t = blockIdx.x, tid = threadIdx.x;
    const float4* xr = (const float4*)(g_x + (size_t)t * ED);
    float4 v = xr[tid];
    float s1 = v.x + v.y + v.z + v.w;
    float s2 = v.x * v.x + v.y * v.y + v.z * v.z + v.w * v.w;
    #pragma unroll
    for (int o = 16; o; o >>= 1) {
        s1 += __shfl_xor_sync(0xffffffffu, s1, o);
        s2 += __shfl_xor_sync(0xffffffffu, s2, o);
    }
    __shared__ float sa[8], sb[8];
    int w = tid >> 5, l = tid & 31;
    if (l == 0) { sa[w] = s1; sb[w] = s2; }
    __syncthreads();
    float s1t = 0.f, s2t = 0.f;
    #pragma unroll
    for (int i = 0; i < 8; i++) { s1t += sa[i]; s2t += sb[i]; }
    float mu = s1t * (1.f / ED);
    float var = fmaxf(s2t * (1.f / ED) - mu * mu, 0.f);
    float inv = rsqrtf(var + 1e-5f);
    float4 gg = ((const float4*)g)[tid];
    float4 bv = ((const float4*)bb)[tid];
    float4 ln;
    ln.x = (v.x - mu) * inv * gg.x + bv.x;
    ln.y = (v.y - mu) * inv * gg.y + bv.y;
    ln.z = (v.z - mu) * inv * gg.z + bv.z;
    ln.w = (v.w - mu) * inv * gg.w + bv.w;
    float ss = ln.x * ln.x + ln.y * ln.y + ln.z * ln.z + ln.w * ln.w;
    float am = fmaxf(fmaxf(fabsf(ln.x), fabsf(ln.y)), fmaxf(fabsf(ln.z), fabsf(ln.w)));
    #pragma unroll
    for (int o = 16; o; o >>= 1) {
        ss += __shfl_xor_sync(0xffffffffu, ss, o);
        am = fmaxf(am, __shfl_xor_sync(0xffffffffu, am, o));
    }
    __syncthreads();
    if (l == 0) { sa[w] = ss; sb[w] = am; }
    __syncthreads();
    float sst = 0.f, amt = 0.f;
    #pragma unroll
    for (int i = 0; i < 8; i++) { sst += sa[i]; amt = fmaxf(amt, sb[i]); }
    float r = 1.f / (sqrtf(sst * (1.f / ED) + 1e-6f) * 32.f);
    float scale = 127.f / fmaxf(amt * r, 1e-5f);
    if (tid == 0) g_fact[t] = 1.f / scale;
    float f = r * scale;
    float qx = fminf(fmaxf(rintf(ln.x * f), -128.f), 127.f);
    float qy = fminf(fmaxf(rintf(ln.y * f), -128.f), 127.f);
    float qz = fminf(fmaxf(rintf(ln.z * f), -128.f), 127.f);
    float qw = fminf(fmaxf(rintf(ln.w * f), -128.f), 127.f);
    uint2 c; c.x = pack_bf2(qx, qy); c.y = pack_bf2(qz, qw);
    ((uint2*)g_actbf)[(size_t)t * (ED / 4) + tid] = c;
}

// ---------------- exact bf16 HMMA GEMM: C[m,n] = alpha*fact[m]*(A·Bᵀ) + bias[n] ----------------
// CTA 128x128, BK=64, 8 warps (warp tile 32x64), double-buffered smem, pitch 72 bf16 (144B).
#define GP   72                    // smem row pitch in bf16
#define BUFB (128 * GP * 2)        // one A-or-B buffer: 18432 B
#define GEMM_SMEM (4 * BUFB)       // A0,B0,A1,B1 = 73728 B

__global__ void __launch_bounds__(256) gemm_mma(int mid, const float* __restrict__ bias,
                                                int Nout, float* __restrict__ Cext) {
    extern __shared__ char SM[];
    uint32_t sbase = smem_u32(SM);
    const __nv_bfloat16* A = g_actbf;
    const __nv_bfloat16* B = sel_w(mid);
    float* C = (mid == 0) ? g_q : (mid == 1) ? g_k : (mid == 2) ? g_v : Cext;
    int tid = threadIdx.x, wid = tid >> 5, lid = tid & 31;
    int wm = wid & 3, wn = wid >> 2;
    int m0 = blockIdx.y * 128, n0 = blockIdx.x * 128;

    // smem byte offsets: [A0][B0][A1][B1]
    auto Aoff = [&](int b) { return (uint32_t)(b * 2 * BUFB); };
    auto Boff = [&](int b) { return (uint32_t)(b * 2 * BUFB + BUFB); };

    int lrow = tid >> 3;               // 0..31 (we loop 4x for 128 rows)
    int lc8  = (tid & 7) * 8;          // bf16 col 0..56

    // preload chunk 0
    {
        const __nv_bfloat16* Ag = A + (size_t)(m0) * ED;
        const __nv_bfloat16* Bg = B + (size_t)(n0) * ED;
        #pragma unroll
        for (int u = 0; u < 4; u++) {
            int row = lrow + u * 32;
            *(uint4*)(SM + Aoff(0) + (row * GP + lc8) * 2) =
                *(const uint4*)(Ag + (size_t)row * ED + lc8);
            *(uint4*)(SM + Boff(0) + (row * GP + lc8) * 2) =
                *(const uint4*)(Bg + (size_t)row * ED + lc8);
        }
    }
    __syncthreads();

    float acc[2][8][4];
    #pragma unroll
    for (int i = 0; i < 2; i++)
        #pragma unroll
        for (int j = 0; j < 8; j++)
            #pragma unroll
            for (int q = 0; q < 4; q++) acc[i][j][q] = 0.f;

    // ldmatrix lane addressing
    int a_r = lid & 15, a_k8 = (lid >> 4) * 8;                       // A: row, k-offset
    int b_n = (lid & 7) + ((lid >> 4) & 1) * 8;                      // B: n within 16
    int b_k8 = ((lid >> 3) & 1) * 8;                                 // B: k-offset

    #pragma unroll 1
    for (int kt = 0; kt < 16; kt++) {
        int cur = kt & 1;
        uint4 pa[4], pb[4];
        if (kt + 1 < 16) {
            const __nv_bfloat16* Ag = A + (size_t)m0 * ED + (kt + 1) * 64;
            const __nv_bfloat16* Bg = B + (size_t)n0 * ED + (kt + 1) * 64;
            #pragma unroll
            for (int u = 0; u < 4; u++) {
                int row = lrow + u * 32;
                pa[u] = *(const uint4*)(Ag + (size_t)row * ED + lc8);
                pb[u] = *(const uint4*)(Bg + (size_t)row * ED + lc8);
            }
        }
        uint32_t sA = sbase + Aoff(cur), sB = sbase + Boff(cur);
        #pragma unroll
        for (int ks = 0; ks < 4; ks++) {
            uint32_t a[2][4];
            #pragma unroll
            for (int mt = 0; mt < 2; mt++) {
                uint32_t ad = sA + ((wm * 32 + mt * 16 + a_r) * GP + ks * 16 + a_k8) * 2;
                LDSM4(a[mt][0], a[mt][1], a[mt][2], a[mt][3], ad);
            }
            #pragma unroll
            for (int np = 0; np < 4; np++) {
                uint32_t b0, b1, b2, b3;
                uint32_t bd = sB + ((wn * 64 + np * 16 + b_n) * GP + ks * 16 + b_k8) * 2;
                LDSM4(b0, b1, b2, b3, bd);
                MMA16816(acc[0][np * 2 + 0], a[0][0], a[0][1], a[0][2], a[0][3], b0, b1);
                MMA16816(acc[0][np * 2 + 1], a[0][0], a[0][1], a[0][2], a[0][3], b2, b3);
                MMA16816(acc[1][np * 2 + 0], a[1][0], a[1][1], a[1][2], a[1][3], b0, b1);
                MMA16816(acc[1][np * 2 + 1], a[1][0], a[1][1], a[1][2], a[1][3], b2, b3);
            }
        }
        if (kt + 1 < 16) {
            int nxt = cur ^ 1;
            #pragma unroll
            for (int u = 0; u < 4; u++) {
                int row = lrow + u * 32;
                *(uint4*)(SM + Aoff(nxt) + (row * GP + lc8) * 2) = pa[u];
                *(uint4*)(SM + Boff(nxt) + (row * GP + lc8) * 2) = pb[u];
            }
            __syncthreads();
        }
    }

    // epilogue
    float alpha = g_alpha[mid];
    int trow = lid >> 2, tcol = (lid & 3) * 2;
    #pragma unroll
    for (int mt = 0; mt < 2; mt++) {
        int r0 = m0 + wm * 32 + mt * 16 + trow;
        float sf0 = alpha * g_fact[r0];
        float sf1 = alpha * g_fact[r0 + 8];
        #pragma unroll
        for (int nt = 0; nt < 8; nt++) {
            int cc = n0 + wn * 64 + nt * 8 + tcol;
            float bx = bias[cc], by = bias[cc + 1];
            float2 o0 = make_float2(acc[mt][nt][0] * sf0 + bx, acc[mt][nt][1] * sf0 + by);
            float2 o1 = make_float2(acc[mt][nt][2] * sf1 + bx, acc[mt][nt][3] * sf1 + by);
            *(float2*)&C[(size_t)r0 * Nout + cc] = o0;
            *(float2*)&C[(size_t)(r0 + 8) * Nout + cc] = o1;
        }
    }
}

// ---------------- fp32 flash attention (GQA, non-causal), f32x2 packed math ----------------
#define AP 132
#define PP 68
__global__ void __launch_bounds__(256) attn_fp32() {
    extern __shared__ char SM[];
    float* smf = (float*)SM;
    float* Qs = smf;
    float* Ks = Qs + 64 * AP;
    float* Vs = Ks + 64 * AP;
    float* Ps = Vs + 64 * AP;   // pitch PP
    int tid = threadIdx.x, tx = tid & 15, ty = tid >> 4;
    int qt = blockIdx.x, bh = blockIdx.y;
    int b = bh >> 3, h = bh & 7, kvh = h >> 2;
    const float* qb = g_q + (size_t)b * SEQ * ED + (size_t)h * HD;
    const float* kb = g_k + (size_t)b * SEQ * KVD + (size_t)kvh * HD;
    const float* vb = g_v + (size_t)b * SEQ * KVD + (size_t)kvh * HD;
    const float qsc = 0.08838834764831845f;  // 1/sqrt(128)
    #pragma unroll
    for (int u = 0; u < 8; u++) {
        int idx = tid + u * 256, row = idx >> 5, d4 = (idx & 31) << 2;
        float4 q = *(const float4*)&qb[(size_t)(qt * 64 + row) * ED + d4];
        q.x *= qsc; q.y *= qsc; q.z *= qsc; q.w *= qsc;
        *(float4*)&Qs[row * AP + d4] = q;
    }
    float m_[4], l_[4];
    unsigned long long acc2[4][4];
    #pragma unroll
    for (int i = 0; i < 4; i++) {
        m_[i] = -1e30f; l_[i] = 0.f;
        #pragma unroll
        for (int p = 0; p < 4; p++) acc2[i][p] = 0ULL;
    }
    for (int kt = 0; kt < 32; kt++) {
        __syncthreads();
        #pragma unroll
        for (int u = 0; u < 8; u++) {
            int idx = tid + u * 256, row = idx >> 5, d4 = (idx & 31) << 2;
            *(float4*)&Ks[row * AP + d4] = *(const float4*)&kb[(size_t)(kt * 64 + row) * KVD + d4];
            *(float4*)&Vs[row * AP + d4] = *(const float4*)&vb[(size_t)(kt * 64 + row) * KVD + d4];
        }
        __syncthreads();
        unsigned long long s2[4][4];
        #pragma unroll
        for (int i = 0; i < 4; i++)
            #pragma unroll
            for (int j = 0; j < 4; j++) s2[i][j] = 0ULL;
        #pragma unroll 4
        for (int d = 0; d < 128; d += 4) {
            ulonglong2 q0 = *(const ulonglong2*)&Qs[(ty * 4 + 0) * AP + d];
            ulonglong2 q1 = *(const ulonglong2*)&Qs[(ty * 4 + 1) * AP + d];
            ulonglong2 q2 = *(const ulonglong2*)&Qs[(ty * 4 + 2) * AP + d];
            ulonglong2 q3 = *(const ulonglong2*)&Qs[(ty * 4 + 3) * AP + d];
            ulonglong2 k0 = *(const ulonglong2*)&Ks[(tx     ) * AP + d];
            ulonglong2 k1 = *(const ulonglong2*)&Ks[(tx + 16) * AP + d];
            ulonglong2 k2 = *(const ulonglong2*)&Ks[(tx + 32) * AP + d];
            ulonglong2 k3 = *(const ulonglong2*)&Ks[(tx + 48) * AP + d];
            FMA2(s2[0][0], q0.x, k0.x); FMA2(s2[0][0], q0.y, k0.y);
            FMA2(s2[0][1], q0.x, k1.x); FMA2(s2[0][1], q0.y, k1.y);
            FMA2(s2[0][2], q0.x, k2.x); FMA2(s2[0][2], q0.y, k2.y);
            FMA2(s2[0][3], q0.x, k3.x); FMA2(s2[0][3], q0.y, k3.y);
            FMA2(s2[1][0], q1.x, k0.x); FMA2(s2[1][0], q1.y, k0.y);
            FMA2(s2[1][1], q1.x, k1.x); FMA2(s2[1][1], q1.y, k1.y);
            FMA2(s2[1][2], q1.x, k2.x); FMA2(s2[1][2], q1.y, k2.y);
            FMA2(s2[1][3], q1.x, k3.x); FMA2(s2[1][3], q1.y, k3.y);
            FMA2(s2[2][0], q2.x, k0.x); FMA2(s2[2][0], q2.y, k0.y);
            FMA2(s2[2][1], q2.x, k1.x); FMA2(s2[2][1], q2.y, k1.y);
            FMA2(s2[2][2], q2.x, k2.x); FMA2(s2[2][2], q2.y, k2.y);
            FMA2(s2[2][3], q2.x, k3.x); FMA2(s2[2][3], q2.y, k3.y);
            FMA2(s2[3][0], q3.x, k0.x); FMA2(s2[3][0], q3.y, k0.y);
            FMA2(s2[3][1], q3.x, k1.x); FMA2(s2[3][1], q3.y, k1.y);
            FMA2(s2[3][2], q3.x, k2.x); FMA2(s2[3][2], q3.y, k2.y);
            FMA2(s2[3][3], q3.x, k3.x); FMA2(s2[3][3], q3.y, k3.y);
        }
        float s[4][4];
        #pragma unroll
        for (int i = 0; i < 4; i++)
            #pragma unroll
            for (int j = 0; j < 4; j++) s[i][j] = lo2(s2[i][j]) + hi2(s2[i][j]);
        #pragma unroll
        for (int i = 0; i < 4; i++) {
            float rm = fmaxf(fmaxf(s[i][0], s[i][1]), fmaxf(s[i][2], s[i][3]));
            #pragma unroll
            for (int o = 8; o; o >>= 1) rm = fmaxf(rm, __shfl_xor_sync(0xffffffffu, rm, o));
            float mn = fmaxf(m_[i], rm);
            float corr = __expf(m_[i] - mn);
            float p0 = __expf(s[i][0] - mn), p1 = __expf(s[i][1] - mn);
            float p2 = __expf(s[i][2] - mn), p3 = __expf(s[i][3] - mn);
            float rs = p0 + p1 + p2 + p3;
            #pragma unroll
            for (int o = 8; o; o >>= 1) rs += __shfl_xor_sync(0xffffffffu, rs, o);
            l_[i] = l_[i] * corr + rs;
            m_[i] = mn;
            unsigned long long corr2 = pk2(corr, corr);
            #pragma unroll
            for (int p = 0; p < 4; p++) MUL2(acc2[i][p], acc2[i][p], corr2);
            int rp = (ty * 4 + i) * PP;
            Ps[rp + tx] = p0; Ps[rp + tx + 16] = p1; Ps[rp + tx + 32] = p2; Ps[rp + tx + 48] = p3;
        }
        __syncthreads();
        #pragma unroll 2
        for (int c = 0; c < 64; c += 4) {
            float4 pr0 = *(const float4*)&Ps[(ty * 4 + 0) * PP + c];
            float4 pr1 = *(const float4*)&Ps[(ty * 4 + 1) * PP + c];
            float4 pr2 = *(const float4*)&Ps[(ty * 4 + 2) * PP + c];
            float4 pr3 = *(const float4*)&Ps[(ty * 4 + 3) * PP + c];
            #define PVC(CI, P0, P1, P2, P3) { \
                ulonglong2 va = *(const ulonglong2*)&Vs[(c + CI) * AP + tx * 8]; \
                ulonglong2 vb2 = *(const ulonglong2*)&Vs[(c + CI) * AP + tx * 8 + 4]; \
                unsigned long long pp; \
                pp = pk2(P0, P0); FMA2(acc2[0][0], pp, va.x); FMA2(acc2[0][1], pp, va.y); \
                                  FMA2(acc2[0][2], pp, vb2.x); FMA2(acc2[0][3], pp, vb2.y); \
                pp = pk2(P1, P1); FMA2(acc2[1][0], pp, va.x); FMA2(acc2[1][1], pp, va.y); \
                                  FMA2(acc2[1][2], pp, vb2.x); FMA2(acc2[1][3], pp, vb2.y); \
                pp = pk2(P2, P2); FMA2(acc2[2][0], pp, va.x); FMA2(acc2[2][1], pp, va.y); \
                                  FMA2(acc2[2][2], pp, vb2.x); FMA2(acc2[2][3], pp, vb2.y); \
                pp = pk2(P3, P3); FMA2(acc2[3][0], pp, va.x); FMA2(acc2[3][1], pp, va.y); \
                                  FMA2(acc2[3][2], pp, vb2.x); FMA2(acc2[3][3], pp, vb2.y); }
            PVC(0, pr0.x, pr1.x, pr2.x, pr3.x)
            PVC(1, pr0.y, pr1.y, pr2.y, pr3.y)
            PVC(2, pr0.z, pr1.z, pr2.z, pr3.z)
            PVC(3, pr0.w, pr1.w, pr2.w, pr3.w)
            #undef PVC
        }
    }
    #pragma unroll
    for (int i = 0; i < 4; i++) {
        float inv = 1.f / l_[i];
        int row = qt * 64 + ty * 4 + i;
        float* xo = g_x + ((size_t)b * SEQ + row) * ED + h * HD + tx * 8;
        float4 o1 = make_float4(lo2(acc2[i][0]) * inv, hi2(acc2[i][0]) * inv,
                                lo2(acc2[i][1]) * inv, hi2(acc2[i][1]) * inv);
        float4 o2 = make_float4(lo2(acc2[i][2]) * inv, hi2(acc2[i][2]) * inv,
                                lo2(acc2[i][3]) * inv, hi2(acc2[i][3]) * inv);
        *(float4*)xo = o1;
        *(float4*)(xo + 4) = o2;
    }
}

// ---------------- launch ----------------
extern "C" void kernel_launch(void* const* d_in, const int* in_sizes, int n_in,
                              void* d_out, int out_size) {
    const float* query = (const float*)d_in[0];
    const float* key   = (const float*)d_in[1];
    const float* value = (const float*)d_in[2];
    const float* q_w   = (const float*)d_in[3];
    const float* q_b   = (const float*)d_in[4];
    const float* k_w   = (const float*)d_in[5];
    const float* k_b   = (const float*)d_in[6];
    const float* v_w   = (const float*)d_in[7];
    const float* v_b   = (const float*)d_in[8];
    const float* ln_g  = (const float*)d_in[9];
    const float* ln_b  = (const float*)d_in[10];
    const float* out_w = (const float*)d_in[11];
    const float* out_b = (const float*)d_in[12];

    cudaFuncSetAttribute(attn_fp32, cudaFuncAttributeMaxDynamicSharedMemorySize, 118784);
    cudaFuncSetAttribute(gemm_mma,  cudaFuncAttributeMaxDynamicSharedMemorySize, GEMM_SMEM);

    // fused weight prep: bf16 sign pack + |w| partial sums
    prep_w<<<256, 256>>>((const float4*)q_w,   ED * ED / 4,  0);
    prep_w<<<256, 256>>>((const float4*)k_w,   KVD * ED / 4, 1);
    prep_w<<<256, 256>>>((const float4*)v_w,   KVD * ED / 4, 2);
    prep_w<<<256, 256>>>((const float4*)out_w, ED * ED / 4,  3);
    absmean_final<<<4, 256>>>();

    // projections (exact bf16 HMMA path)
    quant_rms<<<NTOK, 256>>>(query);
    gemm_mma<<<dim3(ED / 128, NTOK / 128), 256, GEMM_SMEM>>>(0, q_b, ED, nullptr);
    quant_rms<<<NTOK, 256>>>(key);
    gemm_mma<<<dim3(KVD / 128, NTOK / 128), 256, GEMM_SMEM>>>(1, k_b, KVD, nullptr);
    quant_rms<<<NTOK, 256>>>(value);
    gemm_mma<<<dim3(KVD / 128, NTOK / 128), 256, GEMM_SMEM>>>(2, v_b, KVD, nullptr);

    // attention (fp32-exact, f32x2 packed)
    attn_fp32<<<dim3(SEQ / 64, 16), 256, 118784>>>();

    // layernorm + final bitlinear
    ln_quant<<<NTOK, 256>>>(ln_g, ln_b);
    gemm_mma<<<dim3(ED / 128, NTOK / 128), 256, GEMM_SMEM>>>(3, out_b, ED, (float*)d_out);
}

// round 5
// speedup vs baseline: 3.1017x; 2.5800x over previous
#include <cuda_runtime.h>
#include <cuda_bf16.h>
#include <math.h>
#include <stdint.h>

#define SEQ   2048
#define NTOK  4096
#define ED    1024
#define KVD   256
#define HD    128

// ---------------- device scratch (no allocations allowed) ----------------
__device__ float g_alpha[4];
__device__ float g_part[4][256];
__device__ __nv_bfloat16 g_wq[ED*ED];
__device__ __nv_bfloat16 g_wk[KVD*ED];
__device__ __nv_bfloat16 g_wv[KVD*ED];
__device__ __nv_bfloat16 g_wo[ED*ED];
__device__ __nv_bfloat16 g_actbf[NTOK*ED];
__device__ float g_fact[NTOK];
__device__ float g_q[NTOK*ED];
__device__ float g_k[NTOK*KVD];
__device__ float g_v[NTOK*KVD];
__device__ float g_x[NTOK*ED];

__device__ __forceinline__ __nv_bfloat16* sel_w(int m) {
    return m == 0 ? g_wq : m == 1 ? g_wk : m == 2 ? g_wv : g_wo;
}

__device__ __forceinline__ uint32_t smem_u32(const void* p) {
    uint32_t a;
    asm("{ .reg .u64 t; cvta.to.shared.u64 t, %1; cvt.u32.u64 %0, t; }" : "=r"(a) : "l"(p));
    return a;
}
__device__ __forceinline__ unsigned pack_bf2(float a, float b) {
    return (unsigned)__bfloat16_as_ushort(__float2bfloat16_rn(a)) |
           ((unsigned)__bfloat16_as_ushort(__float2bfloat16_rn(b)) << 16);
}

#define LDSM4(R0,R1,R2,R3,ADDR) \
    asm volatile("ldmatrix.sync.aligned.m8n8.x4.shared.b16 {%0,%1,%2,%3}, [%4];" \
        : "=r"(R0), "=r"(R1), "=r"(R2), "=r"(R3) : "r"(ADDR))
#define LDSM4T(R0,R1,R2,R3,ADDR) \
    asm volatile("ldmatrix.sync.aligned.m8n8.x4.trans.shared.b16 {%0,%1,%2,%3}, [%4];" \
        : "=r"(R0), "=r"(R1), "=r"(R2), "=r"(R3) : "r"(ADDR))
#define MMA16816(C, A0,A1,A2,A3, B0,B1) \
    asm volatile("mma.sync.aligned.m16n8k16.row.col.f32.bf16.bf16.f32 " \
        "{%0,%1,%2,%3}, {%4,%5,%6,%7}, {%8,%9}, {%0,%1,%2,%3};" \
        : "+f"((C)[0]), "+f"((C)[1]), "+f"((C)[2]), "+f"((C)[3]) \
        : "r"(A0), "r"(A1), "r"(A2), "r"(A3), "r"(B0), "r"(B1))

// ---------------- fused weight prep: bf16 sign pack + |w| partial sums ----------------
__global__ void prep_w(const float4* __restrict__ w, int n4, int mid) {
    __shared__ float sh[256];
    float s = 0.f;
    uint2* dst = (uint2*)sel_w(mid);
    for (int i = blockIdx.x * 256 + threadIdx.x; i < n4; i += 256 * 256) {
        float4 v = w[i];
        s += fabsf(v.x) + fabsf(v.y) + fabsf(v.z) + fabsf(v.w);
        uint2 c;
        c.x = pack_bf2((float)((v.x > 0.f) - (v.x < 0.f)), (float)((v.y > 0.f) - (v.y < 0.f)));
        c.y = pack_bf2((float)((v.z > 0.f) - (v.z < 0.f)), (float)((v.w > 0.f) - (v.w < 0.f)));
        dst[i] = c;
    }
    sh[threadIdx.x] = s;
    __syncthreads();
    for (int o = 128; o > 0; o >>= 1) {
        if (threadIdx.x < o) sh[threadIdx.x] += sh[threadIdx.x + o];
        __syncthreads();
    }
    if (threadIdx.x == 0) g_part[mid][blockIdx.x] = sh[0];
}

__global__ void absmean_final() {
    int m = blockIdx.x;
    __shared__ float sh[256];
    sh[threadIdx.x] = g_part[m][threadIdx.x];
    __syncthreads();
    for (int o = 128; o > 0; o >>= 1) {
        if (threadIdx.x < o) sh[threadIdx.x] += sh[threadIdx.x + o];
        __syncthreads();
    }
    if (threadIdx.x == 0) {
        float n = (m == 1 || m == 2) ? (float)(KVD * ED) : (float)(ED * ED);
        g_alpha[m] = sh[0] / n;
    }
}

// ---------------- RMSNorm + activation quant (per token) -> bf16 ----------------
__global__ void quant_rms(const float* __restrict__ x) {
    int t = blockIdx.x, tid = threadIdx.x;
    const float4* xr = (const float4*)(x + (size_t)t * ED);
    float4 v = xr[tid];
    float ss = v.x * v.x + v.y * v.y + v.z * v.z + v.w * v.w;
    float am = fmaxf(fmaxf(fabsf(v.x), fabsf(v.y)), fmaxf(fabsf(v.z), fabsf(v.w)));
    #pragma unroll
    for (int o = 16; o; o >>= 1) {
        ss += __shfl_xor_sync(0xffffffffu, ss, o);
        am = fmaxf(am, __shfl_xor_sync(0xffffffffu, am, o));
    }
    __shared__ float sa[8], sb[8];
    int w = tid >> 5, l = tid & 31;
    if (l == 0) { sa[w] = ss; sb[w] = am; }
    __syncthreads();
    float sst = 0.f, amt = 0.f;
    #pragma unroll
    for (int i = 0; i < 8; i++) { sst += sa[i]; amt = fmaxf(amt, sb[i]); }
    float r = 1.f / (sqrtf(sst * (1.f / ED) + 1e-6f) * 32.f);
    float scale = 127.f / fmaxf(amt * r, 1e-5f);
    if (tid == 0) g_fact[t] = 1.f / scale;
    float f = r * scale;
    float qx = fminf(fmaxf(rintf(v.x * f), -128.f), 127.f);
    float qy = fminf(fmaxf(rintf(v.y * f), -128.f), 127.f);
    float qz = fminf(fmaxf(rintf(v.z * f), -128.f), 127.f);
    float qw = fminf(fmaxf(rintf(v.w * f), -128.f), 127.f);
    uint2 c; c.x = pack_bf2(qx, qy); c.y = pack_bf2(qz, qw);
    ((uint2*)g_actbf)[(size_t)t * (ED / 4) + tid] = c;
}

// ---------------- LayerNorm + RMSNorm + activation quant -> bf16 ----------------
__global__ void ln_quant(const float* __restrict__ g, const float* __restrict__ bb) {
    int t = blockIdx.x, tid = threadIdx.x;
    const float4* xr = (const float4*)(g_x + (size_t)t * ED);
    float4 v = xr[tid];
    float s1 = v.x + v.y + v.z + v.w;
    float s2 = v.x * v.x + v.y * v.y + v.z * v.z + v.w * v.w;
    #pragma unroll
    for (int o = 16; o; o >>= 1) {
        s1 += __shfl_xor_sync(0xffffffffu, s1, o);
        s2 += __shfl_xor_sync(0xffffffffu, s2, o);
    }
    __shared__ float sa[8], sb[8];
    int w = tid >> 5, l = tid & 31;
    if (l == 0) { sa[w] = s1; sb[w] = s2; }
    __syncthreads();
    float s1t = 0.f, s2t = 0.f;
    #pragma unroll
    for (int i = 0; i < 8; i++) { s1t += sa[i]; s2t += sb[i]; }
    float mu = s1t * (1.f / ED);
    float var = fmaxf(s2t * (1.f / ED) - mu * mu, 0.f);
    float inv = rsqrtf(var + 1e-5f);
    float4 gg = ((const float4*)g)[tid];
    float4 bv = ((const float4*)bb)[tid];
    float4 ln;
    ln.x = (v.x - mu) * inv * gg.x + bv.x;
    ln.y = (v.y - mu) * inv * gg.y + bv.y;
    ln.z = (v.z - mu) * inv * gg.z + bv.z;
    ln.w = (v.w - mu) * inv * gg.w + bv.w;
    float ss = ln.x * ln.x + ln.y * ln.y + ln.z * ln.z + ln.w * ln.w;
    float am = fmaxf(fmaxf(fabsf(ln.x), fabsf(ln.y)), fmaxf(fabsf(ln.z), fabsf(ln.w)));
    #pragma unroll
    for (int o = 16; o; o >>= 1) {
        ss += __shfl_xor_sync(0xffffffffu, ss, o);
        am = fmaxf(am, __shfl_xor_sync(0xffffffffu, am, o));
    }
    __syncthreads();
    if (l == 0) { sa[w] = ss; sb[w] = am; }
    __syncthreads();
    float sst = 0.f, amt = 0.f;
    #pragma unroll
    for (int i = 0; i < 8; i++) { sst += sa[i]; amt = fmaxf(amt, sb[i]); }
    float r = 1.f / (sqrtf(sst * (1.f / ED) + 1e-6f) * 32.f);
    float scale = 127.f / fmaxf(amt * r, 1e-5f);
    if (tid == 0) g_fact[t] = 1.f / scale;
    float f = r * scale;
    float qx = fminf(fmaxf(rintf(ln.x * f), -128.f), 127.f);
    float qy = fminf(fmaxf(rintf(ln.y * f), -128.f), 127.f);
    float qz = fminf(fmaxf(rintf(ln.z * f), -128.f), 127.f);
    float qw = fminf(fmaxf(rintf(ln.w * f), -128.f), 127.f);
    uint2 c; c.x = pack_bf2(qx, qy); c.y = pack_bf2(qz, qw);
    ((uint2*)g_actbf)[(size_t)t * (ED / 4) + tid] = c;
}

// ---------------- exact bf16 HMMA GEMM: C[m,n] = alpha*fact[m]*(A·Bᵀ) + bias[n] ----------------
#define GP   72
#define BUFB (128 * GP * 2)
#define GEMM_SMEM (4 * BUFB)

__global__ void __launch_bounds__(256) gemm_mma(int mid, const float* __restrict__ bias,
                                                int Nout, float* __restrict__ Cext) {
    extern __shared__ char SM[];
    uint32_t sbase = smem_u32(SM);
    const __nv_bfloat16* A = g_actbf;
    const __nv_bfloat16* B = sel_w(mid);
    float* C = (mid == 0) ? g_q : (mid == 1) ? g_k : (mid == 2) ? g_v : Cext;
    int tid = threadIdx.x, wid = tid >> 5, lid = tid & 31;
    int wm = wid & 3, wn = wid >> 2;
    int m0 = blockIdx.y * 128, n0 = blockIdx.x * 128;

    auto Aoff = [&](int b) { return (uint32_t)(b * 2 * BUFB); };
    auto Boff = [&](int b) { return (uint32_t)(b * 2 * BUFB + BUFB); };

    int lrow = tid >> 3;
    int lc8  = (tid & 7) * 8;

    {
        const __nv_bfloat16* Ag = A + (size_t)(m0) * ED;
        const __nv_bfloat16* Bg = B + (size_t)(n0) * ED;
        #pragma unroll
        for (int u = 0; u < 4; u++) {
            int row = lrow + u * 32;
            *(uint4*)(SM + Aoff(0) + (row * GP + lc8) * 2) =
                *(const uint4*)(Ag + (size_t)row * ED + lc8);
            *(uint4*)(SM + Boff(0) + (row * GP + lc8) * 2) =
                *(const uint4*)(Bg + (size_t)row * ED + lc8);
        }
    }
    __syncthreads();

    float acc[2][8][4];
    #pragma unroll
    for (int i = 0; i < 2; i++)
        #pragma unroll
        for (int j = 0; j < 8; j++)
            #pragma unroll
            for (int q = 0; q < 4; q++) acc[i][j][q] = 0.f;

    int a_r = lid & 15, a_k8 = (lid >> 4) * 8;
    int b_n = (lid & 7) + ((lid >> 4) & 1) * 8;
    int b_k8 = ((lid >> 3) & 1) * 8;

    #pragma unroll 1
    for (int kt = 0; kt < 16; kt++) {
        int cur = kt & 1;
        uint4 pa[4], pb[4];
        if (kt + 1 < 16) {
            const __nv_bfloat16* Ag = A + (size_t)m0 * ED + (kt + 1) * 64;
            const __nv_bfloat16* Bg = B + (size_t)n0 * ED + (kt + 1) * 64;
            #pragma unroll
            for (int u = 0; u < 4; u++) {
                int row = lrow + u * 32;
                pa[u] = *(const uint4*)(Ag + (size_t)row * ED + lc8);
                pb[u] = *(const uint4*)(Bg + (size_t)row * ED + lc8);
            }
        }
        uint32_t sA = sbase + Aoff(cur), sB = sbase + Boff(cur);
        #pragma unroll
        for (int ks = 0; ks < 4; ks++) {
            uint32_t a[2][4];
            #pragma unroll
            for (int mt = 0; mt < 2; mt++) {
                uint32_t ad = sA + ((wm * 32 + mt * 16 + a_r) * GP + ks * 16 + a_k8) * 2;
                LDSM4(a[mt][0], a[mt][1], a[mt][2], a[mt][3], ad);
            }
            #pragma unroll
            for (int np = 0; np < 4; np++) {
                uint32_t b0, b1, b2, b3;
                uint32_t bd = sB + ((wn * 64 + np * 16 + b_n) * GP + ks * 16 + b_k8) * 2;
                LDSM4(b0, b1, b2, b3, bd);
                MMA16816(acc[0][np * 2 + 0], a[0][0], a[0][1], a[0][2], a[0][3], b0, b1);
                MMA16816(acc[0][np * 2 + 1], a[0][0], a[0][1], a[0][2], a[0][3], b2, b3);
                MMA16816(acc[1][np * 2 + 0], a[1][0], a[1][1], a[1][2], a[1][3], b0, b1);
                MMA16816(acc[1][np * 2 + 1], a[1][0], a[1][1], a[1][2], a[1][3], b2, b3);
            }
        }
        if (kt + 1 < 16) {
            int nxt = cur ^ 1;
            #pragma unroll
            for (int u = 0; u < 4; u++) {
                int row = lrow + u * 32;
                *(uint4*)(SM + Aoff(nxt) + (row * GP + lc8) * 2) = pa[u];
                *(uint4*)(SM + Boff(nxt) + (row * GP + lc8) * 2) = pb[u];
            }
            __syncthreads();
        }
    }

    float alpha = g_alpha[mid];
    int trow = lid >> 2, tcol = (lid & 3) * 2;
    #pragma unroll
    for (int mt = 0; mt < 2; mt++) {
        int r0 = m0 + wm * 32 + mt * 16 + trow;
        float sf0 = alpha * g_fact[r0];
        float sf1 = alpha * g_fact[r0 + 8];
        #pragma unroll
        for (int nt = 0; nt < 8; nt++) {
            int cc = n0 + wn * 64 + nt * 8 + tcol;
            float bx = bias[cc], by = bias[cc + 1];
            float2 o0 = make_float2(acc[mt][nt][0] * sf0 + bx, acc[mt][nt][1] * sf0 + by);
            float2 o1 = make_float2(acc[mt][nt][2] * sf1 + bx, acc[mt][nt][3] * sf1 + by);
            *(float2*)&C[(size_t)r0 * Nout + cc] = o0;
            *(float2*)&C[(size_t)(r0 + 8) * Nout + cc] = o1;
        }
    }
}

// ---------------- HMMA flash attention, split-bf16 exact-ish (err ~1e-5) ----------------
// 8 warps, 128 Q rows/CTA (16/warp), KV tiles of 64. K/V/Q split hi+lo bf16; 3 MMAs per product.
#define VP 136                          // smem pitch in bf16 elems (272B rows, conflict-free)
#define S_KHI 0
#define S_KLO (64 * VP)
#define S_VHI (128 * VP)
#define S_VLO (192 * VP)
#define ATTN_SMEM (256 * VP * 2)        // 69632 B

__device__ __forceinline__ void cvt_hl4(float4 v, uint2& hi, uint2& lo) {
    __nv_bfloat16 hx = __float2bfloat16_rn(v.x);
    __nv_bfloat16 hy = __float2bfloat16_rn(v.y);
    __nv_bfloat16 hz = __float2bfloat16_rn(v.z);
    __nv_bfloat16 hw = __float2bfloat16_rn(v.w);
    hi.x = (unsigned)__bfloat16_as_ushort(hx) | ((unsigned)__bfloat16_as_ushort(hy) << 16);
    hi.y = (unsigned)__bfloat16_as_ushort(hz) | ((unsigned)__bfloat16_as_ushort(hw) << 16);
    lo.x = pack_bf2(v.x - __bfloat162float(hx), v.y - __bfloat162float(hy));
    lo.y = pack_bf2(v.z - __bfloat162float(hz), v.w - __bfloat162float(hw));
}

__global__ void __launch_bounds__(256, 1) attn_mma() {
    extern __shared__ __nv_bfloat16 SB[];
    uint32_t sbase = smem_u32(SB);
    int tid = threadIdx.x, wid = tid >> 5, lid = tid & 31;
    int qt = blockIdx.x, bh = blockIdx.y;
    int b = bh >> 3, h = bh & 7, kvh = h >> 2;
    const float* qg = g_q + ((size_t)b * SEQ + qt * 128) * ED + h * HD;
    const float* kg = g_k + (size_t)b * SEQ * KVD + kvh * HD;
    const float* vg = g_v + (size_t)b * SEQ * KVD + kvh * HD;
    const float qsc = 0.08838834764831845f;  // 1/sqrt(128)

    // ---- stage Q (128x128), scaled, as hi/lo bf16 ----
    #pragma unroll
    for (int u = 0; u < 16; u++) {
        int i = tid + u * 256;          // 4096 float4 slots
        int row = i >> 5, c4 = (i & 31) << 2;
        float4 v = *(const float4*)(qg + (size_t)row * ED + c4);
        v.x *= qsc; v.y *= qsc; v.z *= qsc; v.w *= qsc;
        uint2 hi, lo;
        cvt_hl4(v, hi, lo);
        *(uint2*)&SB[S_KHI + row * VP + c4] = hi;   // Qhi staging (rows 0..127)
        *(uint2*)&SB[S_VHI + row * VP + c4] = lo;   // Qlo staging
    }
    __syncthreads();

    // ---- Q fragments to registers ----
    uint32_t qh[8][4], ql[8][4];
    {
        int ar = lid & 15, ak8 = (lid >> 4) * 8;
        #pragma unroll
        for (int j = 0; j < 8; j++) {
            uint32_t adh = sbase + (uint32_t)(S_KHI + (wid * 16 + ar) * VP + j * 16 + ak8) * 2;
            LDSM4(qh[j][0], qh[j][1], qh[j][2], qh[j][3], adh);
            uint32_t adl = sbase + (uint32_t)(S_VHI + (wid * 16 + ar) * VP + j * 16 + ak8) * 2;
            LDSM4(ql[j][0], ql[j][1], ql[j][2], ql[j][3], adl);
        }
    }

    float m_[2] = {-1e30f, -1e30f}, l_[2] = {0.f, 0.f};
    float o[16][4];
    #pragma unroll
    for (int i = 0; i < 16; i++)
        #pragma unroll
        for (int q = 0; q < 4; q++) o[i][q] = 0.f;

    int b_n  = (lid & 7) + ((lid >> 4) & 1) * 8;    // K B-frag n within 16
    int b_k8 = ((lid >> 3) & 1) * 8;                // K B-frag k offset
    int v_r  = lid & 15, v_n8 = (lid >> 4) * 8;     // V trans ldsm addressing

    #pragma unroll 1
    for (int kt = 0; kt < 32; kt++) {
        __syncthreads();   // previous iteration's smem reads (and Q frag loads) done
        // ---- load + convert K/V tile (64 x 128 each) ----
        #pragma unroll
        for (int u = 0; u < 8; u++) {
            int i = tid + u * 256;      // 2048 float4 slots
            int row = i >> 5, c4 = (i & 31) << 2;
            float4 kv = *(const float4*)(kg + (size_t)(kt * 64 + row) * KVD + c4);
            uint2 hi, lo;
            cvt_hl4(kv, hi, lo);
            *(uint2*)&SB[S_KHI + row * VP + c4] = hi;
            *(uint2*)&SB[S_KLO + row * VP + c4] = lo;
            float4 vv = *(const float4*)(vg + (size_t)(kt * 64 + row) * KVD + c4);
            cvt_hl4(vv, hi, lo);
            *(uint2*)&SB[S_VHI + row * VP + c4] = hi;
            *(uint2*)&SB[S_VLO + row * VP + c4] = lo;
        }
        __syncthreads();

        // ---- QK^T: S[16 x 64], 3-way split ----
        float S[8][4];
        #pragma unroll
        for (int nt = 0; nt < 8; nt++)
            #pragma unroll
            for (int q = 0; q < 4; q++) S[nt][q] = 0.f;
        #pragma unroll
        for (int j = 0; j < 8; j++) {
            #pragma unroll
            for (int g = 0; g < 4; g++) {
                uint32_t bh0, bh1, bh2, bh3, bl0, bl1, bl2, bl3;
                uint32_t adh = sbase + (uint32_t)(S_KHI + (g * 16 + b_n) * VP + j * 16 + b_k8) * 2;
                LDSM4(bh0, bh1, bh2, bh3, adh);
                uint32_t adl = sbase + (uint32_t)(S_KLO + (g * 16 + b_n) * VP + j * 16 + b_k8) * 2;
                LDSM4(bl0, bl1, bl2, bl3, adl);
                MMA16816(S[2*g],   qh[j][0], qh[j][1], qh[j][2], qh[j][3], bh0, bh1);
                MMA16816(S[2*g],   qh[j][0], qh[j][1], qh[j][2], qh[j][3], bl0, bl1);
                MMA16816(S[2*g],   ql[j][0], ql[j][1], ql[j][2], ql[j][3], bh0, bh1);
                MMA16816(S[2*g+1], qh[j][0], qh[j][1], qh[j][2], qh[j][3], bh2, bh3);
                MMA16816(S[2*g+1], qh[j][0], qh[j][1], qh[j][2], qh[j][3], bl2, bl3);
                MMA16816(S[2*g+1], ql[j][0], ql[j][1], ql[j][2], ql[j][3], bh2, bh3);
            }
        }

        // ---- online softmax (per row; quad reduction) ----
        #pragma unroll
        for (int rr = 0; rr < 2; rr++) {
            int c0 = rr * 2;
            float mx = -1e30f;
            #pragma unroll
            for (int nt = 0; nt < 8; nt++)
                mx = fmaxf(mx, fmaxf(S[nt][c0], S[nt][c0 + 1]));
            mx = fmaxf(mx, __shfl_xor_sync(0xffffffffu, mx, 1));
            mx = fmaxf(mx, __shfl_xor_sync(0xffffffffu, mx, 2));
            float mn = fmaxf(m_[rr], mx);
            float corr = __expf(m_[rr] - mn);
            m_[rr] = mn;
            float sum = 0.f;
            #pragma unroll
            for (int nt = 0; nt < 8; nt++) {
                float p0 = __expf(S[nt][c0] - mn);
                float p1 = __expf(S[nt][c0 + 1] - mn);
                S[nt][c0] = p0; S[nt][c0 + 1] = p1;
                sum += p0 + p1;
            }
            sum += __shfl_xor_sync(0xffffffffu, sum, 1);
            sum += __shfl_xor_sync(0xffffffffu, sum, 2);
            l_[rr] = l_[rr] * corr + sum;
            #pragma unroll
            for (int nt = 0; nt < 16; nt++) {
                o[nt][c0] *= corr; o[nt][c0 + 1] *= corr;
            }
        }

        // ---- pack P as A-fragments, hi/lo ----
        uint32_t ph[4][4], pl[4][4];
        #pragma unroll
        for (int jp = 0; jp < 4; jp++) {
            #pragma unroll
            for (int q = 0; q < 4; q++) {
                int nt = 2 * jp + (q >> 1);
                int c0 = (q & 1) * 2;
                float x = S[nt][c0], y = S[nt][c0 + 1];
                __nv_bfloat16 hx = __float2bfloat16_rn(x);
                __nv_bfloat16 hy = __float2bfloat16_rn(y);
                ph[jp][q] = (unsigned)__bfloat16_as_ushort(hx) |
                            ((unsigned)__bfloat16_as_ushort(hy) << 16);
                pl[jp][q] = pack_bf2(x - __bfloat162float(hx), y - __bfloat162float(hy));
            }
        }

        // ---- PV: O[16 x 128] += P · V, 3-way split ----
        #pragma unroll
        for (int jp = 0; jp < 4; jp++) {
            #pragma unroll
            for (int g = 0; g < 8; g++) {
                uint32_t vh0, vh1, vh2, vh3, vl0, vl1, vl2, vl3;
                uint32_t adh = sbase + (uint32_t)(S_VHI + (jp * 16 + v_r) * VP + g * 16 + v_n8) * 2;
                LDSM4T(vh0, vh1, vh2, vh3, adh);
                uint32_t adl = sbase + (uint32_t)(S_VLO + (jp * 16 + v_r) * VP + g * 16 + v_n8) * 2;
                LDSM4T(vl0, vl1, vl2, vl3, adl);
                MMA16816(o[2*g],   ph[jp][0], ph[jp][1], ph[jp][2], ph[jp][3], vh0, vh1);
                MMA16816(o[2*g],   ph[jp][0], ph[jp][1], ph[jp][2], ph[jp][3], vl0, vl1);
                MMA16816(o[2*g],   pl[jp][0], pl[jp][1], pl[jp][2], pl[jp][3], vh0, vh1);
                MMA16816(o[2*g+1], ph[jp][0], ph[jp][1], ph[jp][2], ph[jp][3], vh2, vh3);
                MMA16816(o[2*g+1], ph[jp][0], ph[jp][1], ph[jp][2], ph[jp][3], vl2, vl3);
                MMA16816(o[2*g+1], pl[jp][0], pl[jp][1], pl[jp][2], pl[jp][3], vh2, vh3);
            }
        }
    }

    // ---- epilogue ----
    #pragma unroll
    for (int rr = 0; rr < 2; rr++) {
        float inv = 1.f / l_[rr];
        int srow = qt * 128 + wid * 16 + (lid >> 2) + rr * 8;
        float* xo = g_x + ((size_t)b * SEQ + srow) * ED + h * HD;
        #pragma unroll
        for (int nt = 0; nt < 16; nt++) {
            int col = nt * 8 + (lid & 3) * 2;
            *(float2*)&xo[col] = make_float2(o[nt][rr * 2] * inv, o[nt][rr * 2 + 1] * inv);
        }
    }
}

// ---------------- launch ----------------
extern "C" void kernel_launch(void* const* d_in, const int* in_sizes, int n_in,
                              void* d_out, int out_size) {
    const float* query = (const float*)d_in[0];
    const float* key   = (const float*)d_in[1];
    const float* value = (const float*)d_in[2];
    const float* q_w   = (const float*)d_in[3];
    const float* q_b   = (const float*)d_in[4];
    const float* k_w   = (const float*)d_in[5];
    const float* k_b   = (const float*)d_in[6];
    const float* v_w   = (const float*)d_in[7];
    const float* v_b   = (const float*)d_in[8];
    const float* ln_g  = (const float*)d_in[9];
    const float* ln_b  = (const float*)d_in[10];
    const float* out_w = (const float*)d_in[11];
    const float* out_b = (const float*)d_in[12];

    cudaFuncSetAttribute(attn_mma, cudaFuncAttributeMaxDynamicSharedMemorySize, ATTN_SMEM);
    cudaFuncSetAttribute(gemm_mma, cudaFuncAttributeMaxDynamicSharedMemorySize, GEMM_SMEM);

    // fused weight prep: bf16 sign pack + |w| partial sums
    prep_w<<<256, 256>>>((const float4*)q_w,   ED * ED / 4,  0);
    prep_w<<<256, 256>>>((const float4*)k_w,   KVD * ED / 4, 1);
    prep_w<<<256, 256>>>((const float4*)v_w,   KVD * ED / 4, 2);
    prep_w<<<256, 256>>>((const float4*)out_w, ED * ED / 4,  3);
    absmean_final<<<4, 256>>>();

    // projections (exact bf16 HMMA path)
    quant_rms<<<NTOK, 256>>>(query);
    gemm_mma<<<dim3(ED / 128, NTOK / 128), 256, GEMM_SMEM>>>(0, q_b, ED, nullptr);
    quant_rms<<<NTOK, 256>>>(key);
    gemm_mma<<<dim3(KVD / 128, NTOK / 128), 256, GEMM_SMEM>>>(1, k_b, KVD, nullptr);
    quant_rms<<<NTOK, 256>>>(value);
    gemm_mma<<<dim3(KVD / 128, NTOK / 128), 256, GEMM_SMEM>>>(2, v_b, KVD, nullptr);

    // attention (HMMA, split-bf16)
    attn_mma<<<dim3(SEQ / 128, 16), 256, ATTN_SMEM>>>();

    // layernorm + final bitlinear
    ln_quant<<<NTOK, 256>>>(ln_g, ln_b);
    gemm_mma<<<dim3(ED / 128, NTOK / 128), 256, GEMM_SMEM>>>(3, out_b, ED, (float*)d_out);
}

// round 6
// speedup vs baseline: 3.5097x; 1.1315x over previous
#include <cuda_runtime.h>
#include <cuda_bf16.h>
#include <math.h>
#include <stdint.h>

#define SEQ   2048
#define NTOK  4096
#define ED    1024
#define KVD   256
#define HD    128
#define QSC   0.08838834764831845f   // 1/sqrt(128)

// ---------------- device scratch (no allocations allowed) ----------------
__device__ float g_alpha[4];
__device__ float g_part[4][256];
__device__ __nv_bfloat16 g_wq[ED*ED];
__device__ __nv_bfloat16 g_wk[KVD*ED];
__device__ __nv_bfloat16 g_wv[KVD*ED];
__device__ __nv_bfloat16 g_wo[ED*ED];
__device__ __nv_bfloat16 g_actbf[NTOK*ED];
__device__ float g_fact[NTOK];
__device__ __nv_bfloat16 g_qhi[NTOK*ED];
__device__ __nv_bfloat16 g_qlo[NTOK*ED];
__device__ __nv_bfloat16 g_khi[NTOK*KVD];
__device__ __nv_bfloat16 g_klo[NTOK*KVD];
__device__ __nv_bfloat16 g_vhi[NTOK*KVD];
__device__ __nv_bfloat16 g_vlo[NTOK*KVD];
__device__ float g_x[NTOK*ED];

__device__ __forceinline__ __nv_bfloat16* sel_w(int m) {
    return m == 0 ? g_wq : m == 1 ? g_wk : m == 2 ? g_wv : g_wo;
}

__device__ __forceinline__ uint32_t smem_u32(const void* p) {
    uint32_t a;
    asm("{ .reg .u64 t; cvta.to.shared.u64 t, %1; cvt.u32.u64 %0, t; }" : "=r"(a) : "l"(p));
    return a;
}
__device__ __forceinline__ unsigned pack_bf2(float a, float b) {
    return (unsigned)__bfloat16_as_ushort(__float2bfloat16_rn(a)) |
           ((unsigned)__bfloat16_as_ushort(__float2bfloat16_rn(b)) << 16);
}

#define LDSM4(R0,R1,R2,R3,ADDR) \
    asm volatile("ldmatrix.sync.aligned.m8n8.x4.shared.b16 {%0,%1,%2,%3}, [%4];" \
        : "=r"(R0), "=r"(R1), "=r"(R2), "=r"(R3) : "r"(ADDR))
#define LDSM4T(R0,R1,R2,R3,ADDR) \
    asm volatile("ldmatrix.sync.aligned.m8n8.x4.trans.shared.b16 {%0,%1,%2,%3}, [%4];" \
        : "=r"(R0), "=r"(R1), "=r"(R2), "=r"(R3) : "r"(ADDR))
#define MMA16816(C, A0,A1,A2,A3, B0,B1) \
    asm volatile("mma.sync.aligned.m16n8k16.row.col.f32.bf16.bf16.f32 " \
        "{%0,%1,%2,%3}, {%4,%5,%6,%7}, {%8,%9}, {%0,%1,%2,%3};" \
        : "+f"((C)[0]), "+f"((C)[1]), "+f"((C)[2]), "+f"((C)[3]) \
        : "r"(A0), "r"(A1), "r"(A2), "r"(A3), "r"(B0), "r"(B1))
#define CP16(SM_, GP_) \
    asm volatile("cp.async.cg.shared.global [%0], [%1], 16;" :: "r"(SM_), "l"(GP_))
#define CPCOMMIT() asm volatile("cp.async.commit_group;" ::: "memory")
#define CPWAIT1()  asm volatile("cp.async.wait_group 1;" ::: "memory")
#define CPWAIT0()  asm volatile("cp.async.wait_group 0;" ::: "memory")

// ---------------- fused weight prep: bf16 sign pack + |w| partial sums ----------------
__global__ void prep_w(const float4* __restrict__ w, int n4, int mid) {
    __shared__ float sh[256];
    float s = 0.f;
    uint2* dst = (uint2*)sel_w(mid);
    for (int i = blockIdx.x * 256 + threadIdx.x; i < n4; i += 256 * 256) {
        float4 v = w[i];
        s += fabsf(v.x) + fabsf(v.y) + fabsf(v.z) + fabsf(v.w);
        uint2 c;
        c.x = pack_bf2((float)((v.x > 0.f) - (v.x < 0.f)), (float)((v.y > 0.f) - (v.y < 0.f)));
        c.y = pack_bf2((float)((v.z > 0.f) - (v.z < 0.f)), (float)((v.w > 0.f) - (v.w < 0.f)));
        dst[i] = c;
    }
    sh[threadIdx.x] = s;
    __syncthreads();
    for (int o = 128; o > 0; o >>= 1) {
        if (threadIdx.x < o) sh[threadIdx.x] += sh[threadIdx.x + o];
        __syncthreads();
    }
    if (threadIdx.x == 0) g_part[mid][blockIdx.x] = sh[0];
}

__global__ void absmean_final() {
    int m = blockIdx.x;
    __shared__ float sh[256];
    sh[threadIdx.x] = g_part[m][threadIdx.x];
    __syncthreads();
    for (int o = 128; o > 0; o >>= 1) {
        if (threadIdx.x < o) sh[threadIdx.x] += sh[threadIdx.x + o];
        __syncthreads();
    }
    if (threadIdx.x == 0) {
        float n = (m == 1 || m == 2) ? (float)(KVD * ED) : (float)(ED * ED);
        g_alpha[m] = sh[0] / n;
    }
}

// ---------------- RMSNorm + activation quant (per token) -> bf16 ----------------
__global__ void quant_rms(const float* __restrict__ x) {
    int t = blockIdx.x, tid = threadIdx.x;
    const float4* xr = (const float4*)(x + (size_t)t * ED);
    float4 v = xr[tid];
    float ss = v.x * v.x + v.y * v.y + v.z * v.z + v.w * v.w;
    float am = fmaxf(fmaxf(fabsf(v.x), fabsf(v.y)), fmaxf(fabsf(v.z), fabsf(v.w)));
    #pragma unroll
    for (int o = 16; o; o >>= 1) {
        ss += __shfl_xor_sync(0xffffffffu, ss, o);
        am = fmaxf(am, __shfl_xor_sync(0xffffffffu, am, o));
    }
    __shared__ float sa[8], sb[8];
    int w = tid >> 5, l = tid & 31;
    if (l == 0) { sa[w] = ss; sb[w] = am; }
    __syncthreads();
    float sst = 0.f, amt = 0.f;
    #pragma unroll
    for (int i = 0; i < 8; i++) { sst += sa[i]; amt = fmaxf(amt, sb[i]); }
    float r = 1.f / (sqrtf(sst * (1.f / ED) + 1e-6f) * 32.f);
    float scale = 127.f / fmaxf(amt * r, 1e-5f);
    if (tid == 0) g_fact[t] = 1.f / scale;
    float f = r * scale;
    float qx = fminf(fmaxf(rintf(v.x * f), -128.f), 127.f);
    float qy = fminf(fmaxf(rintf(v.y * f), -128.f), 127.f);
    float qz = fminf(fmaxf(rintf(v.z * f), -128.f), 127.f);
    float qw = fminf(fmaxf(rintf(v.w * f), -128.f), 127.f);
    uint2 c; c.x = pack_bf2(qx, qy); c.y = pack_bf2(qz, qw);
    ((uint2*)g_actbf)[(size_t)t * (ED / 4) + tid] = c;
}

// ---------------- LayerNorm + RMSNorm + activation quant -> bf16 ----------------
__global__ void ln_quant(const float* __restrict__ g, const float* __restrict__ bb) {
    int t = blockIdx.x, tid = threadIdx.x;
    const float4* xr = (const float4*)(g_x + (size_t)t * ED);
    float4 v = xr[tid];
    float s1 = v.x + v.y + v.z + v.w;
    float s2 = v.x * v.x + v.y * v.y + v.z * v.z + v.w * v.w;
    #pragma unroll
    for (int o = 16; o; o >>= 1) {
        s1 += __shfl_xor_sync(0xffffffffu, s1, o);
        s2 += __shfl_xor_sync(0xffffffffu, s2, o);
    }
    __shared__ float sa[8], sb[8];
    int w = tid >> 5, l = tid & 31;
    if (l == 0) { sa[w] = s1; sb[w] = s2; }
    __syncthreads();
    float s1t = 0.f, s2t = 0.f;
    #pragma unroll
    for (int i = 0; i < 8; i++) { s1t += sa[i]; s2t += sb[i]; }
    float mu = s1t * (1.f / ED);
    float var = fmaxf(s2t * (1.f / ED) - mu * mu, 0.f);
    float inv = rsqrtf(var + 1e-5f);
    float4 gg = ((const float4*)g)[tid];
    float4 bv = ((const float4*)bb)[tid];
    float4 ln;
    ln.x = (v.x - mu) * inv * gg.x + bv.x;
    ln.y = (v.y - mu) * inv * gg.y + bv.y;
    ln.z = (v.z - mu) * inv * gg.z + bv.z;
    ln.w = (v.w - mu) * inv * gg.w + bv.w;
    float ss = ln.x * ln.x + ln.y * ln.y + ln.z * ln.z + ln.w * ln.w;
    float am = fmaxf(fmaxf(fabsf(ln.x), fabsf(ln.y)), fmaxf(fabsf(ln.z), fabsf(ln.w)));
    #pragma unroll
    for (int o = 16; o; o >>= 1) {
        ss += __shfl_xor_sync(0xffffffffu, ss, o);
        am = fmaxf(am, __shfl_xor_sync(0xffffffffu, am, o));
    }
    __syncthreads();
    if (l == 0) { sa[w] = ss; sb[w] = am; }
    __syncthreads();
    float sst = 0.f, amt = 0.f;
    #pragma unroll
    for (int i = 0; i < 8; i++) { sst += sa[i]; amt = fmaxf(amt, sb[i]); }
    float r = 1.f / (sqrtf(sst * (1.f / ED) + 1e-6f) * 32.f);
    float scale = 127.f / fmaxf(amt * r, 1e-5f);
    if (tid == 0) g_fact[t] = 1.f / scale;
    float f = r * scale;
    float qx = fminf(fmaxf(rintf(ln.x * f), -128.f), 127.f);
    float qy = fminf(fmaxf(rintf(ln.y * f), -128.f), 127.f);
    float qz = fminf(fmaxf(rintf(ln.z * f), -128.f), 127.f);
    float qw = fminf(fmaxf(rintf(ln.w * f), -128.f), 127.f);
    uint2 c; c.x = pack_bf2(qx, qy); c.y = pack_bf2(qz, qw);
    ((uint2*)g_actbf)[(size_t)t * (ED / 4) + tid] = c;
}

// ---------------- exact bf16 HMMA GEMM, epilogue writes hi/lo bf16 (or fp32 for out) ------
#define GP   72
#define BUFB (128 * GP * 2)
#define GEMM_SMEM (4 * BUFB)

__global__ void __launch_bounds__(256) gemm_mma(int mid, const float* __restrict__ bias,
                                                int Nout, float* __restrict__ Cext) {
    extern __shared__ char SM[];
    uint32_t sbase = smem_u32(SM);
    const __nv_bfloat16* A = g_actbf;
    const __nv_bfloat16* B = sel_w(mid);
    int tid = threadIdx.x, wid = tid >> 5, lid = tid & 31;
    int wm = wid & 3, wn = wid >> 2;
    int m0 = blockIdx.y * 128, n0 = blockIdx.x * 128;

    auto Aoff = [&](int b) { return (uint32_t)(b * 2 * BUFB); };
    auto Boff = [&](int b) { return (uint32_t)(b * 2 * BUFB + BUFB); };

    int lrow = tid >> 3;
    int lc8  = (tid & 7) * 8;

    {
        const __nv_bfloat16* Ag = A + (size_t)(m0) * ED;
        const __nv_bfloat16* Bg = B + (size_t)(n0) * ED;
        #pragma unroll
        for (int u = 0; u < 4; u++) {
            int row = lrow + u * 32;
            *(uint4*)(SM + Aoff(0) + (row * GP + lc8) * 2) =
                *(const uint4*)(Ag + (size_t)row * ED + lc8);
            *(uint4*)(SM + Boff(0) + (row * GP + lc8) * 2) =
                *(const uint4*)(Bg + (size_t)row * ED + lc8);
        }
    }
    __syncthreads();

    float acc[2][8][4];
    #pragma unroll
    for (int i = 0; i < 2; i++)
        #pragma unroll
        for (int j = 0; j < 8; j++)
            #pragma unroll
            for (int q = 0; q < 4; q++) acc[i][j][q] = 0.f;

    int a_r = lid & 15, a_k8 = (lid >> 4) * 8;
    int b_n = (lid & 7) + ((lid >> 4) & 1) * 8;
    int b_k8 = ((lid >> 3) & 1) * 8;

    #pragma unroll 1
    for (int kt = 0; kt < 16; kt++) {
        int cur = kt & 1;
        uint4 pa[4], pb[4];
        if (kt + 1 < 16) {
            const __nv_bfloat16* Ag = A + (size_t)m0 * ED + (kt + 1) * 64;
            const __nv_bfloat16* Bg = B + (size_t)n0 * ED + (kt + 1) * 64;
            #pragma unroll
            for (int u = 0; u < 4; u++) {
                int row = lrow + u * 32;
                pa[u] = *(const uint4*)(Ag + (size_t)row * ED + lc8);
                pb[u] = *(const uint4*)(Bg + (size_t)row * ED + lc8);
            }
        }
        uint32_t sA = sbase + Aoff(cur), sB = sbase + Boff(cur);
        #pragma unroll
        for (int ks = 0; ks < 4; ks++) {
            uint32_t a[2][4];
            #pragma unroll
            for (int mt = 0; mt < 2; mt++) {
                uint32_t ad = sA + ((wm * 32 + mt * 16 + a_r) * GP + ks * 16 + a_k8) * 2;
                LDSM4(a[mt][0], a[mt][1], a[mt][2], a[mt][3], ad);
            }
            #pragma unroll
            for (int np = 0; np < 4; np++) {
                uint32_t b0, b1, b2, b3;
                uint32_t bd = sB + ((wn * 64 + np * 16 + b_n) * GP + ks * 16 + b_k8) * 2;
                LDSM4(b0, b1, b2, b3, bd);
                MMA16816(acc[0][np * 2 + 0], a[0][0], a[0][1], a[0][2], a[0][3], b0, b1);
                MMA16816(acc[0][np * 2 + 1], a[0][0], a[0][1], a[0][2], a[0][3], b2, b3);
                MMA16816(acc[1][np * 2 + 0], a[1][0], a[1][1], a[1][2], a[1][3], b0, b1);
                MMA16816(acc[1][np * 2 + 1], a[1][0], a[1][1], a[1][2], a[1][3], b2, b3);
            }
        }
        if (kt + 1 < 16) {
            int nxt = cur ^ 1;
            #pragma unroll
            for (int u = 0; u < 4; u++) {
                int row = lrow + u * 32;
                *(uint4*)(SM + Aoff(nxt) + (row * GP + lc8) * 2) = pa[u];
                *(uint4*)(SM + Boff(nxt) + (row * GP + lc8) * 2) = pb[u];
            }
            __syncthreads();
        }
    }

    // ---- epilogue: fp32 value c = acc*alpha*fact*qmul + bias*qmul; write hi/lo bf16 or fp32 ----
    float alpha = g_alpha[mid];
    float qmul = (mid == 0) ? QSC : 1.f;
    __nv_bfloat16* Hp = (mid == 0) ? g_qhi : (mid == 1) ? g_khi : g_vhi;
    __nv_bfloat16* Lp = (mid == 0) ? g_qlo : (mid == 1) ? g_klo : g_vlo;
    int trow = lid >> 2, tcol = (lid & 3) * 2;
    #pragma unroll
    for (int mt = 0; mt < 2; mt++) {
        int r0 = m0 + wm * 32 + mt * 16 + trow;
        float sf0 = alpha * qmul * g_fact[r0];
        float sf1 = alpha * qmul * g_fact[r0 + 8];
        #pragma unroll
        for (int nt = 0; nt < 8; nt++) {
            int cc = n0 + wn * 64 + nt * 8 + tcol;
            float bx = bias[cc] * qmul, by = bias[cc + 1] * qmul;
            float c00 = acc[mt][nt][0] * sf0 + bx, c01 = acc[mt][nt][1] * sf0 + by;
            float c10 = acc[mt][nt][2] * sf1 + bx, c11 = acc[mt][nt][3] * sf1 + by;
            if (mid == 3) {
                *(float2*)&Cext[(size_t)r0 * Nout + cc] = make_float2(c00, c01);
                *(float2*)&Cext[(size_t)(r0 + 8) * Nout + cc] = make_float2(c10, c11);
            } else {
                __nv_bfloat16 h00 = __float2bfloat16_rn(c00), h01 = __float2bfloat16_rn(c01);
                __nv_bfloat16 h10 = __float2bfloat16_rn(c10), h11 = __float2bfloat16_rn(c11);
                *(uint*)&Hp[(size_t)r0 * Nout + cc] =
                    (unsigned)__bfloat16_as_ushort(h00) | ((unsigned)__bfloat16_as_ushort(h01) << 16);
                *(uint*)&Hp[(size_t)(r0 + 8) * Nout + cc] =
                    (unsigned)__bfloat16_as_ushort(h10) | ((unsigned)__bfloat16_as_ushort(h11) << 16);
                *(uint*)&Lp[(size_t)r0 * Nout + cc] =
                    pack_bf2(c00 - __bfloat162float(h00), c01 - __bfloat162float(h01));
                *(uint*)&Lp[(size_t)(r0 + 8) * Nout + cc] =
                    pack_bf2(c10 - __bfloat162float(h10), c11 - __bfloat162float(h11));
            }
        }
    }
}

// ---------------- HMMA flash attention, split-bf16, cp.async double-buffered ----------------
#define VP 136
#define BUF_ELE (256 * VP)                 // one buffer: 4 sections x 64 rows
#define ATTN_SMEM (2 * BUF_ELE * 2)        // 139264 B

__global__ void __launch_bounds__(256, 1) attn_mma() {
    extern __shared__ __nv_bfloat16 SB[];
    uint32_t sbase = smem_u32(SB);
    int tid = threadIdx.x, wid = tid >> 5, lid = tid & 31;
    int qt = blockIdx.x, bh = blockIdx.y;
    int b = bh >> 3, h = bh & 7, kvh = h >> 2;
    const __nv_bfloat16* qhig = g_qhi + ((size_t)b * SEQ + qt * 128) * ED + h * HD;
    const __nv_bfloat16* qlog = g_qlo + ((size_t)b * SEQ + qt * 128) * ED + h * HD;
    const __nv_bfloat16* khig = g_khi + (size_t)b * SEQ * KVD + kvh * HD;
    const __nv_bfloat16* klog = g_klo + (size_t)b * SEQ * KVD + kvh * HD;
    const __nv_bfloat16* vhig = g_vhi + (size_t)b * SEQ * KVD + kvh * HD;
    const __nv_bfloat16* vlog = g_vlo + (size_t)b * SEQ * KVD + kvh * HD;

    // ---- issue KV tile via cp.async into buffer `buf` ----
    auto issue = [&](int kt, int buf) {
        uint32_t sb0 = sbase + (uint32_t)(buf * BUF_ELE) * 2;
        #pragma unroll
        for (int sec = 0; sec < 4; sec++) {
            const __nv_bfloat16* gb = (sec == 0) ? khig : (sec == 1) ? klog
                                     : (sec == 2) ? vhig : vlog;
            #pragma unroll
            for (int u = 0; u < 4; u++) {
                int jj = tid + u * 256;
                int row = jj >> 4, c8 = (jj & 15) * 8;
                const __nv_bfloat16* gp = gb + (size_t)(kt * 64 + row) * KVD + c8;
                uint32_t sm = sb0 + (uint32_t)((sec * 64 + row) * VP + c8) * 2;
                CP16(sm, gp);
            }
        }
    };

    // ---- stage Q (pre-scaled, pre-split) into buffer 1; issue tile 0 into buffer 0 ----
    #pragma unroll
    for (int u = 0; u < 8; u++) {
        int i = tid + u * 256;
        int row = i >> 4, c8 = (i & 15) * 8;
        *(uint4*)&SB[BUF_ELE + row * VP + c8] = *(const uint4*)(qhig + (size_t)row * ED + c8);
        *(uint4*)&SB[BUF_ELE + (128 + row) * VP + c8] = *(const uint4*)(qlog + (size_t)row * ED + c8);
    }
    issue(0, 0);
    CPCOMMIT();
    __syncthreads();

    // ---- Q fragments to registers (from buffer 1) ----
    uint32_t qh[8][4], ql[8][4];
    {
        int ar = lid & 15, ak8 = (lid >> 4) * 8;
        #pragma unroll
        for (int j = 0; j < 8; j++) {
            uint32_t adh = sbase + (uint32_t)(BUF_ELE + (wid * 16 + ar) * VP + j * 16 + ak8) * 2;
            LDSM4(qh[j][0], qh[j][1], qh[j][2], qh[j][3], adh);
            uint32_t adl = sbase + (uint32_t)(BUF_ELE + (128 + wid * 16 + ar) * VP + j * 16 + ak8) * 2;
            LDSM4(ql[j][0], ql[j][1], ql[j][2], ql[j][3], adl);
        }
    }
    __syncthreads();   // buffer 1 free for tile 1

    float m_[2] = {-1e30f, -1e30f}, l_[2] = {0.f, 0.f};
    float o[16][4];
    #pragma unroll
    for (int i = 0; i < 16; i++)
        #pragma unroll
        for (int q = 0; q < 4; q++) o[i][q] = 0.f;

    int b_n  = (lid & 7) + ((lid >> 4) & 1) * 8;
    int b_k8 = ((lid >> 3) & 1) * 8;
    int v_r  = lid & 15, v_n8 = (lid >> 4) * 8;

    #pragma unroll 1
    for (int kt = 0; kt < 32; kt++) {
        if (kt + 1 < 32) { issue(kt + 1, (kt + 1) & 1); CPCOMMIT(); }
        if (kt + 1 < 32) { CPWAIT1(); } else { CPWAIT0(); }
        __syncthreads();
        uint32_t kb = (uint32_t)((kt & 1) * BUF_ELE);
        uint32_t sKH = kb, sKL = kb + 64 * VP, sVH = kb + 128 * VP, sVL = kb + 192 * VP;

        // ---- QK^T: S[16 x 64], 3-way split ----
        float S[8][4];
        #pragma unroll
        for (int nt = 0; nt < 8; nt++)
            #pragma unroll
            for (int q = 0; q < 4; q++) S[nt][q] = 0.f;
        #pragma unroll
        for (int j = 0; j < 8; j++) {
            #pragma unroll
            for (int g = 0; g < 4; g++) {
                uint32_t bh0, bh1, bh2, bh3, bl0, bl1, bl2, bl3;
                uint32_t adh = sbase + (uint32_t)(sKH + (g * 16 + b_n) * VP + j * 16 + b_k8) * 2;
                LDSM4(bh0, bh1, bh2, bh3, adh);
                uint32_t adl = sbase + (uint32_t)(sKL + (g * 16 + b_n) * VP + j * 16 + b_k8) * 2;
                LDSM4(bl0, bl1, bl2, bl3, adl);
                MMA16816(S[2*g],   qh[j][0], qh[j][1], qh[j][2], qh[j][3], bh0, bh1);
                MMA16816(S[2*g],   qh[j][0], qh[j][1], qh[j][2], qh[j][3], bl0, bl1);
                MMA16816(S[2*g],   ql[j][0], ql[j][1], ql[j][2], ql[j][3], bh0, bh1);
                MMA16816(S[2*g+1], qh[j][0], qh[j][1], qh[j][2], qh[j][3], bh2, bh3);
                MMA16816(S[2*g+1], qh[j][0], qh[j][1], qh[j][2], qh[j][3], bl2, bl3);
                MMA16816(S[2*g+1], ql[j][0], ql[j][1], ql[j][2], ql[j][3], bh2, bh3);
            }
        }

        // ---- online softmax ----
        #pragma unroll
        for (int rr = 0; rr < 2; rr++) {
            int c0 = rr * 2;
            float mx = -1e30f;
            #pragma unroll
            for (int nt = 0; nt < 8; nt++)
                mx = fmaxf(mx, fmaxf(S[nt][c0], S[nt][c0 + 1]));
            mx = fmaxf(mx, __shfl_xor_sync(0xffffffffu, mx, 1));
            mx = fmaxf(mx, __shfl_xor_sync(0xffffffffu, mx, 2));
            float mn = fmaxf(m_[rr], mx);
            float corr = __expf(m_[rr] - mn);
            m_[rr] = mn;
            float sum = 0.f;
            #pragma unroll
            for (int nt = 0; nt < 8; nt++) {
                float p0 = __expf(S[nt][c0] - mn);
                float p1 = __expf(S[nt][c0 + 1] - mn);
                S[nt][c0] = p0; S[nt][c0 + 1] = p1;
                sum += p0 + p1;
            }
            sum += __shfl_xor_sync(0xffffffffu, sum, 1);
            sum += __shfl_xor_sync(0xffffffffu, sum, 2);
            l_[rr] = l_[rr] * corr + sum;
            #pragma unroll
            for (int nt = 0; nt < 16; nt++) {
                o[nt][c0] *= corr; o[nt][c0 + 1] *= corr;
            }
        }

        // ---- pack P as A-fragments, hi/lo ----
        uint32_t ph[4][4], pl[4][4];
        #pragma unroll
        for (int jp = 0; jp < 4; jp++) {
            #pragma unroll
            for (int q = 0; q < 4; q++) {
                int nt = 2 * jp + (q >> 1);
                int c0 = (q & 1) * 2;
                float x = S[nt][c0], y = S[nt][c0 + 1];
                __nv_bfloat16 hx = __float2bfloat16_rn(x);
                __nv_bfloat16 hy = __float2bfloat16_rn(y);
                ph[jp][q] = (unsigned)__bfloat16_as_ushort(hx) |
                            ((unsigned)__bfloat16_as_ushort(hy) << 16);
                pl[jp][q] = pack_bf2(x - __bfloat162float(hx), y - __bfloat162float(hy));
            }
        }

        // ---- PV: O += P · V, 3-way split ----
        #pragma unroll
        for (int jp = 0; jp < 4; jp++) {
            #pragma unroll
            for (int g = 0; g < 8; g++) {
                uint32_t vh0, vh1, vh2, vh3, vl0, vl1, vl2, vl3;
                uint32_t adh = sbase + (uint32_t)(sVH + (jp * 16 + v_r) * VP + g * 16 + v_n8) * 2;
                LDSM4T(vh0, vh1, vh2, vh3, adh);
                uint32_t adl = sbase + (uint32_t)(sVL + (jp * 16 + v_r) * VP + g * 16 + v_n8) * 2;
                LDSM4T(vl0, vl1, vl2, vl3, adl);
                MMA16816(o[2*g],   ph[jp][0], ph[jp][1], ph[jp][2], ph[jp][3], vh0, vh1);
                MMA16816(o[2*g],   ph[jp][0], ph[jp][1], ph[jp][2], ph[jp][3], vl0, vl1);
                MMA16816(o[2*g],   pl[jp][0], pl[jp][1], pl[jp][2], pl[jp][3], vh0, vh1);
                MMA16816(o[2*g+1], ph[jp][0], ph[jp][1], ph[jp][2], ph[jp][3], vh2, vh3);
                MMA16816(o[2*g+1], ph[jp][0], ph[jp][1], ph[jp][2], ph[jp][3], vl2, vl3);
                MMA16816(o[2*g+1], pl[jp][0], pl[jp][1], pl[jp][2], pl[jp][3], vh2, vh3);
            }
        }
        __syncthreads();   // all warps done reading buf[kt&1] before iter kt+2 overwrites
    }

    // ---- epilogue ----
    #pragma unroll
    for (int rr = 0; rr < 2; rr++) {
        float inv = 1.f / l_[rr];
        int srow = qt * 128 + wid * 16 + (lid >> 2) + rr * 8;
        float* xo = g_x + ((size_t)b * SEQ + srow) * ED + h * HD;
        #pragma unroll
        for (int nt = 0; nt < 16; nt++) {
            int col = nt * 8 + (lid & 3) * 2;
            *(float2*)&xo[col] = make_float2(o[nt][rr * 2] * inv, o[nt][rr * 2 + 1] * inv);
        }
    }
}

// ---------------- launch ----------------
extern "C" void kernel_launch(void* const* d_in, const int* in_sizes, int n_in,
                              void* d_out, int out_size) {
    const float* query = (const float*)d_in[0];
    const float* key   = (const float*)d_in[1];
    const float* value = (const float*)d_in[2];
    const float* q_w   = (const float*)d_in[3];
    const float* q_b   = (const float*)d_in[4];
    const float* k_w   = (const float*)d_in[5];
    const float* k_b   = (const float*)d_in[6];
    const float* v_w   = (const float*)d_in[7];
    const float* v_b   = (const float*)d_in[8];
    const float* ln_g  = (const float*)d_in[9];
    const float* ln_b  = (const float*)d_in[10];
    const float* out_w = (const float*)d_in[11];
    const float* out_b = (const float*)d_in[12];

    cudaFuncSetAttribute(attn_mma, cudaFuncAttributeMaxDynamicSharedMemorySize, ATTN_SMEM);
    cudaFuncSetAttribute(gemm_mma, cudaFuncAttributeMaxDynamicSharedMemorySize, GEMM_SMEM);

    // fused weight prep
    prep_w<<<256, 256>>>((const float4*)q_w,   ED * ED / 4,  0);
    prep_w<<<256, 256>>>((const float4*)k_w,   KVD * ED / 4, 1);
    prep_w<<<256, 256>>>((const float4*)v_w,   KVD * ED / 4, 2);
    prep_w<<<256, 256>>>((const float4*)out_w, ED * ED / 4,  3);
    absmean_final<<<4, 256>>>();

    // projections -> pre-split hi/lo bf16 (Q pre-scaled by 1/sqrt(128))
    quant_rms<<<NTOK, 256>>>(query);
    gemm_mma<<<dim3(ED / 128, NTOK / 128), 256, GEMM_SMEM>>>(0, q_b, ED, nullptr);
    quant_rms<<<NTOK, 256>>>(key);
    gemm_mma<<<dim3(KVD / 128, NTOK / 128), 256, GEMM_SMEM>>>(1, k_b, KVD, nullptr);
    quant_rms<<<NTOK, 256>>>(value);
    gemm_mma<<<dim3(KVD / 128, NTOK / 128), 256, GEMM_SMEM>>>(2, v_b, KVD, nullptr);

    // attention (HMMA split-bf16, cp.async pipelined)
    attn_mma<<<dim3(SEQ / 128, 16), 256, ATTN_SMEM>>>();

    // layernorm + final bitlinear
    ln_quant<<<NTOK, 256>>>(ln_g, ln_b);
    gemm_mma<<<dim3(ED / 128, NTOK / 128), 256, GEMM_SMEM>>>(3, out_b, ED, (float*)d_out);
}

// round 7
// speedup vs baseline: 3.8343x; 1.0925x over previous
#include <cuda_runtime.h>
#include <cuda_bf16.h>
#include <math.h>
#include <stdint.h>

#define SEQ   2048
#define NTOK  4096
#define ED    1024
#define KVD   256
#define HD    128
#define QSC   0.08838834764831845f   // 1/sqrt(128)

// ---------------- device scratch (no allocations allowed) ----------------
__device__ float g_alpha[4];
__device__ float g_part[4][256];
__device__ __nv_bfloat16 g_wq[ED*ED];
__device__ __nv_bfloat16 g_wk[KVD*ED];
__device__ __nv_bfloat16 g_wv[KVD*ED];
__device__ __nv_bfloat16 g_wo[ED*ED];
__device__ __nv_bfloat16 g_actbf[3*NTOK*ED];   // slot 0:q(=out later) 1:k 2:v
__device__ float g_fact[3*NTOK];
__device__ __nv_bfloat16 g_qhi[NTOK*ED];
__device__ __nv_bfloat16 g_qlo[NTOK*ED];
__device__ __nv_bfloat16 g_khi[NTOK*KVD];
__device__ __nv_bfloat16 g_klo[NTOK*KVD];
__device__ __nv_bfloat16 g_vhi[NTOK*KVD];
__device__ __nv_bfloat16 g_vlo[NTOK*KVD];
__device__ float g_x[NTOK*ED];

__device__ __forceinline__ __nv_bfloat16* sel_w(int m) {
    return m == 0 ? g_wq : m == 1 ? g_wk : m == 2 ? g_wv : g_wo;
}

__device__ __forceinline__ uint32_t smem_u32(const void* p) {
    uint32_t a;
    asm("{ .reg .u64 t; cvta.to.shared.u64 t, %1; cvt.u32.u64 %0, t; }" : "=r"(a) : "l"(p));
    return a;
}
__device__ __forceinline__ unsigned pack_bf2(float a, float b) {
    return (unsigned)__bfloat16_as_ushort(__float2bfloat16_rn(a)) |
           ((unsigned)__bfloat16_as_ushort(__float2bfloat16_rn(b)) << 16);
}

#define LDSM4(R0,R1,R2,R3,ADDR) \
    asm volatile("ldmatrix.sync.aligned.m8n8.x4.shared.b16 {%0,%1,%2,%3}, [%4];" \
        : "=r"(R0), "=r"(R1), "=r"(R2), "=r"(R3) : "r"(ADDR))
#define LDSM4T(R0,R1,R2,R3,ADDR) \
    asm volatile("ldmatrix.sync.aligned.m8n8.x4.trans.shared.b16 {%0,%1,%2,%3}, [%4];" \
        : "=r"(R0), "=r"(R1), "=r"(R2), "=r"(R3) : "r"(ADDR))
#define MMA16816(C, A0,A1,A2,A3, B0,B1) \
    asm volatile("mma.sync.aligned.m16n8k16.row.col.f32.bf16.bf16.f32 " \
        "{%0,%1,%2,%3}, {%4,%5,%6,%7}, {%8,%9}, {%0,%1,%2,%3};" \
        : "+f"((C)[0]), "+f"((C)[1]), "+f"((C)[2]), "+f"((C)[3]) \
        : "r"(A0), "r"(A1), "r"(A2), "r"(A3), "r"(B0), "r"(B1))
#define CP16(SM_, GP_) \
    asm volatile("cp.async.cg.shared.global [%0], [%1], 16;" :: "r"(SM_), "l"(GP_))
#define CPCOMMIT() asm volatile("cp.async.commit_group;" ::: "memory")
#define CPWAIT1()  asm volatile("cp.async.wait_group 1;" ::: "memory")
#define CPWAIT0()  asm volatile("cp.async.wait_group 0;" ::: "memory")

// ---------------- fused weight prep (one launch, grid.y = mid) ----------------
__global__ void prep_w(const float4* __restrict__ w0, const float4* __restrict__ w1,
                       const float4* __restrict__ w2, const float4* __restrict__ w3) {
    __shared__ float sh[256];
    int mid = blockIdx.y;
    const float4* w = mid == 0 ? w0 : mid == 1 ? w1 : mid == 2 ? w2 : w3;
    int n4 = (mid == 1 || mid == 2) ? (KVD * ED / 4) : (ED * ED / 4);
    float s = 0.f;
    uint2* dst = (uint2*)sel_w(mid);
    for (int i = blockIdx.x * 256 + threadIdx.x; i < n4; i += 256 * 256) {
        float4 v = w[i];
        s += fabsf(v.x) + fabsf(v.y) + fabsf(v.z) + fabsf(v.w);
        uint2 c;
        c.x = pack_bf2((float)((v.x > 0.f) - (v.x < 0.f)), (float)((v.y > 0.f) - (v.y < 0.f)));
        c.y = pack_bf2((float)((v.z > 0.f) - (v.z < 0.f)), (float)((v.w > 0.f) - (v.w < 0.f)));
        dst[i] = c;
    }
    sh[threadIdx.x] = s;
    __syncthreads();
    for (int o = 128; o > 0; o >>= 1) {
        if (threadIdx.x < o) sh[threadIdx.x] += sh[threadIdx.x + o];
        __syncthreads();
    }
    if (threadIdx.x == 0) g_part[mid][blockIdx.x] = sh[0];
}

__global__ void absmean_final() {
    int m = blockIdx.x;
    __shared__ float sh[256];
    sh[threadIdx.x] = g_part[m][threadIdx.x];
    __syncthreads();
    for (int o = 128; o > 0; o >>= 1) {
        if (threadIdx.x < o) sh[threadIdx.x] += sh[threadIdx.x + o];
        __syncthreads();
    }
    if (threadIdx.x == 0) {
        float n = (m == 1 || m == 2) ? (float)(KVD * ED) : (float)(ED * ED);
        g_alpha[m] = sh[0] / n;
    }
}

// ---------------- RMSNorm + activation quant (one launch: q,k,v via grid.y) ----------------
__global__ void quant_rms(const float* __restrict__ q, const float* __restrict__ k,
                          const float* __restrict__ vv) {
    int slot = blockIdx.y;
    const float* x = slot == 0 ? q : slot == 1 ? k : vv;
    int t = blockIdx.x, tid = threadIdx.x;
    const float4* xr = (const float4*)(x + (size_t)t * ED);
    float4 v = xr[tid];
    float ss = v.x * v.x + v.y * v.y + v.z * v.z + v.w * v.w;
    float am = fmaxf(fmaxf(fabsf(v.x), fabsf(v.y)), fmaxf(fabsf(v.z), fabsf(v.w)));
    #pragma unroll
    for (int o = 16; o; o >>= 1) {
        ss += __shfl_xor_sync(0xffffffffu, ss, o);
        am = fmaxf(am, __shfl_xor_sync(0xffffffffu, am, o));
    }
    __shared__ float sa[8], sb[8];
    int w = tid >> 5, l = tid & 31;
    if (l == 0) { sa[w] = ss; sb[w] = am; }
    __syncthreads();
    float sst = 0.f, amt = 0.f;
    #pragma unroll
    for (int i = 0; i < 8; i++) { sst += sa[i]; amt = fmaxf(amt, sb[i]); }
    float r = 1.f / (sqrtf(sst * (1.f / ED) + 1e-6f) * 32.f);
    float scale = 127.f / fmaxf(amt * r, 1e-5f);
    if (tid == 0) g_fact[slot * NTOK + t] = 1.f / scale;
    float f = r * scale;
    float qx = fminf(fmaxf(rintf(v.x * f), -128.f), 127.f);
    float qy = fminf(fmaxf(rintf(v.y * f), -128.f), 127.f);
    float qz = fminf(fmaxf(rintf(v.z * f), -128.f), 127.f);
    float qw = fminf(fmaxf(rintf(v.w * f), -128.f), 127.f);
    uint2 c; c.x = pack_bf2(qx, qy); c.y = pack_bf2(qz, qw);
    ((uint2*)g_actbf)[(size_t)slot * NTOK * (ED / 4) + (size_t)t * (ED / 4) + tid] = c;
}

// ---------------- LayerNorm + RMSNorm + activation quant -> bf16 (slot 0) ----------------
__global__ void ln_quant(const float* __restrict__ g, const float* __restrict__ bb) {
    int t = blockIdx.x, tid = threadIdx.x;
    const float4* xr = (const float4*)(g_x + (size_t)t * ED);
    float4 v = xr[tid];
    float s1 = v.x + v.y + v.z + v.w;
    float s2 = v.x * v.x + v.y * v.y + v.z * v.z + v.w * v.w;
    #pragma unroll
    for (int o = 16; o; o >>= 1) {
        s1 += __shfl_xor_sync(0xffffffffu, s1, o);
        s2 += __shfl_xor_sync(0xffffffffu, s2, o);
    }
    __shared__ float sa[8], sb[8];
    int w = tid >> 5, l = tid & 31;
    if (l == 0) { sa[w] = s1; sb[w] = s2; }
    __syncthreads();
    float s1t = 0.f, s2t = 0.f;
    #pragma unroll
    for (int i = 0; i < 8; i++) { s1t += sa[i]; s2t += sb[i]; }
    float mu = s1t * (1.f / ED);
    float var = fmaxf(s2t * (1.f / ED) - mu * mu, 0.f);
    float inv = rsqrtf(var + 1e-5f);
    float4 gg = ((const float4*)g)[tid];
    float4 bv = ((const float4*)bb)[tid];
    float4 ln;
    ln.x = (v.x - mu) * inv * gg.x + bv.x;
    ln.y = (v.y - mu) * inv * gg.y + bv.y;
    ln.z = (v.z - mu) * inv * gg.z + bv.z;
    ln.w = (v.w - mu) * inv * gg.w + bv.w;
    float ss = ln.x * ln.x + ln.y * ln.y + ln.z * ln.z + ln.w * ln.w;
    float am = fmaxf(fmaxf(fabsf(ln.x), fabsf(ln.y)), fmaxf(fabsf(ln.z), fabsf(ln.w)));
    #pragma unroll
    for (int o = 16; o; o >>= 1) {
        ss += __shfl_xor_sync(0xffffffffu, ss, o);
        am = fmaxf(am, __shfl_xor_sync(0xffffffffu, am, o));
    }
    __syncthreads();
    if (l == 0) { sa[w] = ss; sb[w] = am; }
    __syncthreads();
    float sst = 0.f, amt = 0.f;
    #pragma unroll
    for (int i = 0; i < 8; i++) { sst += sa[i]; amt = fmaxf(amt, sb[i]); }
    float r = 1.f / (sqrtf(sst * (1.f / ED) + 1e-6f) * 32.f);
    float scale = 127.f / fmaxf(amt * r, 1e-5f);
    if (tid == 0) g_fact[t] = 1.f / scale;
    float f = r * scale;
    float qx = fminf(fmaxf(rintf(ln.x * f), -128.f), 127.f);
    float qy = fminf(fmaxf(rintf(ln.y * f), -128.f), 127.f);
    float qz = fminf(fmaxf(rintf(ln.z * f), -128.f), 127.f);
    float qw = fminf(fmaxf(rintf(ln.w * f), -128.f), 127.f);
    uint2 c; c.x = pack_bf2(qx, qy); c.y = pack_bf2(qz, qw);
    ((uint2*)g_actbf)[(size_t)t * (ED / 4) + tid] = c;
}

// ---------------- exact bf16 HMMA GEMM body ----------------
#define GP   72
#define BUFB (128 * GP * 2)
#define GEMM_SMEM (4 * BUFB)

__device__ __forceinline__ void gemm_body(int mid, const float* __restrict__ bias,
                                          int Nout, float* __restrict__ Cext,
                                          int bm, int bn, char* SM) {
    uint32_t sbase = smem_u32(SM);
    int aslot = (mid == 3) ? 0 : mid;
    const __nv_bfloat16* A = g_actbf + (size_t)aslot * NTOK * ED;
    const __nv_bfloat16* B = sel_w(mid);
    int tid = threadIdx.x, wid = tid >> 5, lid = tid & 31;
    int wm = wid & 3, wn = wid >> 2;
    int m0 = bm * 128, n0 = bn * 128;

    auto Aoff = [&](int b) { return (uint32_t)(b * 2 * BUFB); };
    auto Boff = [&](int b) { return (uint32_t)(b * 2 * BUFB + BUFB); };

    int lrow = tid >> 3;
    int lc8  = (tid & 7) * 8;

    {
        const __nv_bfloat16* Ag = A + (size_t)(m0) * ED;
        const __nv_bfloat16* Bg = B + (size_t)(n0) * ED;
        #pragma unroll
        for (int u = 0; u < 4; u++) {
            int row = lrow + u * 32;
            *(uint4*)(SM + Aoff(0) + (row * GP + lc8) * 2) =
                *(const uint4*)(Ag + (size_t)row * ED + lc8);
            *(uint4*)(SM + Boff(0) + (row * GP + lc8) * 2) =
                *(const uint4*)(Bg + (size_t)row * ED + lc8);
        }
    }
    __syncthreads();

    float acc[2][8][4];
    #pragma unroll
    for (int i = 0; i < 2; i++)
        #pragma unroll
        for (int j = 0; j < 8; j++)
            #pragma unroll
            for (int q = 0; q < 4; q++) acc[i][j][q] = 0.f;

    int a_r = lid & 15, a_k8 = (lid >> 4) * 8;
    int b_n = (lid & 7) + ((lid >> 4) & 1) * 8;
    int b_k8 = ((lid >> 3) & 1) * 8;

    #pragma unroll 1
    for (int kt = 0; kt < 16; kt++) {
        int cur = kt & 1;
        uint4 pa[4], pb[4];
        if (kt + 1 < 16) {
            const __nv_bfloat16* Ag = A + (size_t)m0 * ED + (kt + 1) * 64;
            const __nv_bfloat16* Bg = B + (size_t)n0 * ED + (kt + 1) * 64;
            #pragma unroll
            for (int u = 0; u < 4; u++) {
                int row = lrow + u * 32;
                pa[u] = *(const uint4*)(Ag + (size_t)row * ED + lc8);
                pb[u] = *(const uint4*)(Bg + (size_t)row * ED + lc8);
            }
        }
        uint32_t sA = sbase + Aoff(cur), sB = sbase + Boff(cur);
        #pragma unroll
        for (int ks = 0; ks < 4; ks++) {
            uint32_t a[2][4];
            #pragma unroll
            for (int mt = 0; mt < 2; mt++) {
                uint32_t ad = sA + ((wm * 32 + mt * 16 + a_r) * GP + ks * 16 + a_k8) * 2;
                LDSM4(a[mt][0], a[mt][1], a[mt][2], a[mt][3], ad);
            }
            #pragma unroll
            for (int np = 0; np < 4; np++) {
                uint32_t b0, b1, b2, b3;
                uint32_t bd = sB + ((wn * 64 + np * 16 + b_n) * GP + ks * 16 + b_k8) * 2;
                LDSM4(b0, b1, b2, b3, bd);
                MMA16816(acc[0][np * 2 + 0], a[0][0], a[0][1], a[0][2], a[0][3], b0, b1);
                MMA16816(acc[0][np * 2 + 1], a[0][0], a[0][1], a[0][2], a[0][3], b2, b3);
                MMA16816(acc[1][np * 2 + 0], a[1][0], a[1][1], a[1][2], a[1][3], b0, b1);
                MMA16816(acc[1][np * 2 + 1], a[1][0], a[1][1], a[1][2], a[1][3], b2, b3);
            }
        }
        if (kt + 1 < 16) {
            int nxt = cur ^ 1;
            #pragma unroll
            for (int u = 0; u < 4; u++) {
                int row = lrow + u * 32;
                *(uint4*)(SM + Aoff(nxt) + (row * GP + lc8) * 2) = pa[u];
                *(uint4*)(SM + Boff(nxt) + (row * GP + lc8) * 2) = pb[u];
            }
            __syncthreads();
        }
    }

    float alpha = g_alpha[mid];
    float qmul = (mid == 0) ? QSC : 1.f;
    __nv_bfloat16* Hp = (mid == 0) ? g_qhi : (mid == 1) ? g_khi : g_vhi;
    __nv_bfloat16* Lp = (mid == 0) ? g_qlo : (mid == 1) ? g_klo : g_vlo;
    int trow = lid >> 2, tcol = (lid & 3) * 2;
    #pragma unroll
    for (int mt = 0; mt < 2; mt++) {
        int r0 = m0 + wm * 32 + mt * 16 + trow;
        float sf0 = alpha * qmul * g_fact[aslot * NTOK + r0];
        float sf1 = alpha * qmul * g_fact[aslot * NTOK + r0 + 8];
        #pragma unroll
        for (int nt = 0; nt < 8; nt++) {
            int cc = n0 + wn * 64 + nt * 8 + tcol;
            float bx = bias[cc] * qmul, by = bias[cc + 1] * qmul;
            float c00 = acc[mt][nt][0] * sf0 + bx, c01 = acc[mt][nt][1] * sf0 + by;
            float c10 = acc[mt][nt][2] * sf1 + bx, c11 = acc[mt][nt][3] * sf1 + by;
            if (mid == 3) {
                *(float2*)&Cext[(size_t)r0 * Nout + cc] = make_float2(c00, c01);
                *(float2*)&Cext[(size_t)(r0 + 8) * Nout + cc] = make_float2(c10, c11);
            } else {
                __nv_bfloat16 h00 = __float2bfloat16_rn(c00), h01 = __float2bfloat16_rn(c01);
                __nv_bfloat16 h10 = __float2bfloat16_rn(c10), h11 = __float2bfloat16_rn(c11);
                *(uint*)&Hp[(size_t)r0 * Nout + cc] =
                    (unsigned)__bfloat16_as_ushort(h00) | ((unsigned)__bfloat16_as_ushort(h01) << 16);
                *(uint*)&Hp[(size_t)(r0 + 8) * Nout + cc] =
                    (unsigned)__bfloat16_as_ushort(h10) | ((unsigned)__bfloat16_as_ushort(h11) << 16);
                *(uint*)&Lp[(size_t)r0 * Nout + cc] =
                    pack_bf2(c00 - __bfloat162float(h00), c01 - __bfloat162float(h01));
                *(uint*)&Lp[(size_t)(r0 + 8) * Nout + cc] =
                    pack_bf2(c10 - __bfloat162float(h10), c11 - __bfloat162float(h11));
            }
        }
    }
}

// combined q+k+v projections in one launch (384 CTAs)
__global__ void __launch_bounds__(256) gemm_qkv(const float* __restrict__ qb,
                                                const float* __restrict__ kb,
                                                const float* __restrict__ vb) {
    extern __shared__ char SM[];
    int item = blockIdx.x;
    int mid, bm, bn, Nout;
    const float* bias;
    if (item < 256)      { mid = 0; bias = qb; Nout = ED;  bm = item >> 3;        bn = item & 7; }
    else if (item < 320) { mid = 1; bias = kb; Nout = KVD; bm = (item - 256) >> 1; bn = (item - 256) & 1; }
    else                 { mid = 2; bias = vb; Nout = KVD; bm = (item - 320) >> 1; bn = (item - 320) & 1; }
    gemm_body(mid, bias, Nout, nullptr, bm, bn, SM);
}

__global__ void __launch_bounds__(256) gemm_out(const float* __restrict__ bias,
                                                float* __restrict__ Cext) {
    extern __shared__ char SM[];
    gemm_body(3, bias, ED, Cext, blockIdx.x >> 3, blockIdx.x & 7, SM);
}

// ---------------- HMMA flash attention, split-bf16, cp.async double-buffered ----------------
#define VP 136
#define BUF_ELE (256 * VP)
#define ATTN_SMEM (2 * BUF_ELE * 2)        // 139264 B

__global__ void __launch_bounds__(256, 1) attn_mma() {
    extern __shared__ __nv_bfloat16 SB[];
    uint32_t sbase = smem_u32(SB);
    int tid = threadIdx.x, wid = tid >> 5, lid = tid & 31;
    int qt = blockIdx.x, bh = blockIdx.y;
    int b = bh >> 3, h = bh & 7, kvh = h >> 2;
    const __nv_bfloat16* qhig = g_qhi + ((size_t)b * SEQ + qt * 128) * ED + h * HD;
    const __nv_bfloat16* qlog = g_qlo + ((size_t)b * SEQ + qt * 128) * ED + h * HD;
    const __nv_bfloat16* khig = g_khi + (size_t)b * SEQ * KVD + kvh * HD;
    const __nv_bfloat16* klog = g_klo + (size_t)b * SEQ * KVD + kvh * HD;
    const __nv_bfloat16* vhig = g_vhi + (size_t)b * SEQ * KVD + kvh * HD;
    const __nv_bfloat16* vlog = g_vlo + (size_t)b * SEQ * KVD + kvh * HD;

    auto issue = [&](int kt, int buf) {
        uint32_t sb0 = sbase + (uint32_t)(buf * BUF_ELE) * 2;
        #pragma unroll
        for (int sec = 0; sec < 4; sec++) {
            const __nv_bfloat16* gb = (sec == 0) ? khig : (sec == 1) ? klog
                                     : (sec == 2) ? vhig : vlog;
            #pragma unroll
            for (int u = 0; u < 4; u++) {
                int jj = tid + u * 256;
                int row = jj >> 4, c8 = (jj & 15) * 8;
                const __nv_bfloat16* gp = gb + (size_t)(kt * 64 + row) * KVD + c8;
                uint32_t sm = sb0 + (uint32_t)((sec * 64 + row) * VP + c8) * 2;
                CP16(sm, gp);
            }
        }
    };

    #pragma unroll
    for (int u = 0; u < 8; u++) {
        int i = tid + u * 256;
        int row = i >> 4, c8 = (i & 15) * 8;
        *(uint4*)&SB[BUF_ELE + row * VP + c8] = *(const uint4*)(qhig + (size_t)row * ED + c8);
        *(uint4*)&SB[BUF_ELE + (128 + row) * VP + c8] = *(const uint4*)(qlog + (size_t)row * ED + c8);
    }
    issue(0, 0);
    CPCOMMIT();
    __syncthreads();

    uint32_t qh[8][4], ql[8][4];
    {
        int ar = lid & 15, ak8 = (lid >> 4) * 8;
        #pragma unroll
        for (int j = 0; j < 8; j++) {
            uint32_t adh = sbase + (uint32_t)(BUF_ELE + (wid * 16 + ar) * VP + j * 16 + ak8) * 2;
            LDSM4(qh[j][0], qh[j][1], qh[j][2], qh[j][3], adh);
            uint32_t adl = sbase + (uint32_t)(BUF_ELE + (128 + wid * 16 + ar) * VP + j * 16 + ak8) * 2;
            LDSM4(ql[j][0], ql[j][1], ql[j][2], ql[j][3], adl);
        }
    }
    __syncthreads();

    float m_[2] = {-1e30f, -1e30f}, l_[2] = {0.f, 0.f};
    float o[16][4];
    #pragma unroll
    for (int i = 0; i < 16; i++)
        #pragma unroll
        for (int q = 0; q < 4; q++) o[i][q] = 0.f;

    int b_n  = (lid & 7) + ((lid >> 4) & 1) * 8;
    int b_k8 = ((lid >> 3) & 1) * 8;
    int v_r  = lid & 15, v_n8 = (lid >> 4) * 8;

    #pragma unroll 1
    for (int kt = 0; kt < 32; kt++) {
        if (kt + 1 < 32) { issue(kt + 1, (kt + 1) & 1); CPCOMMIT(); }
        if (kt + 1 < 32) { CPWAIT1(); } else { CPWAIT0(); }
        __syncthreads();
        uint32_t kb = (uint32_t)((kt & 1) * BUF_ELE);
        uint32_t sKH = kb, sKL = kb + 64 * VP, sVH = kb + 128 * VP, sVL = kb + 192 * VP;

        float S[8][4];
        #pragma unroll
        for (int nt = 0; nt < 8; nt++)
            #pragma unroll
            for (int q = 0; q < 4; q++) S[nt][q] = 0.f;
        #pragma unroll
        for (int j = 0; j < 8; j++) {
            #pragma unroll
            for (int g = 0; g < 4; g++) {
                uint32_t bh0, bh1, bh2, bh3, bl0, bl1, bl2, bl3;
                uint32_t adh = sbase + (uint32_t)(sKH + (g * 16 + b_n) * VP + j * 16 + b_k8) * 2;
                LDSM4(bh0, bh1, bh2, bh3, adh);
                uint32_t adl = sbase + (uint32_t)(sKL + (g * 16 + b_n) * VP + j * 16 + b_k8) * 2;
                LDSM4(bl0, bl1, bl2, bl3, adl);
                MMA16816(S[2*g],   qh[j][0], qh[j][1], qh[j][2], qh[j][3], bh0, bh1);
                MMA16816(S[2*g],   qh[j][0], qh[j][1], qh[j][2], qh[j][3], bl0, bl1);
                MMA16816(S[2*g],   ql[j][0], ql[j][1], ql[j][2], ql[j][3], bh0, bh1);
                MMA16816(S[2*g+1], qh[j][0], qh[j][1], qh[j][2], qh[j][3], bh2, bh3);
                MMA16816(S[2*g+1], qh[j][0], qh[j][1], qh[j][2], qh[j][3], bl2, bl3);
                MMA16816(S[2*g+1], ql[j][0], ql[j][1], ql[j][2], ql[j][3], bh2, bh3);
            }
        }

        // ---- online softmax with skip-rescale ----
        #pragma unroll
        for (int rr = 0; rr < 2; rr++) {
            int c0 = rr * 2;
            float mx = -1e30f;
            #pragma unroll
            for (int nt = 0; nt < 8; nt++)
                mx = fmaxf(mx, fmaxf(S[nt][c0], S[nt][c0 + 1]));
            mx = fmaxf(mx, __shfl_xor_sync(0xffffffffu, mx, 1));
            mx = fmaxf(mx, __shfl_xor_sync(0xffffffffu, mx, 2));
            if (mx > m_[rr]) {
                float corr = __expf(m_[rr] - mx);
                m_[rr] = mx;
                l_[rr] *= corr;
                #pragma unroll
                for (int nt = 0; nt < 16; nt++) {
                    o[nt][c0] *= corr; o[nt][c0 + 1] *= corr;
                }
            }
            float mn = m_[rr];
            float sum = 0.f;
            #pragma unroll
            for (int nt = 0; nt < 8; nt++) {
                float p0 = __expf(S[nt][c0] - mn);
                float p1 = __expf(S[nt][c0 + 1] - mn);
                S[nt][c0] = p0; S[nt][c0 + 1] = p1;
                sum += p0 + p1;
            }
            sum += __shfl_xor_sync(0xffffffffu, sum, 1);
            sum += __shfl_xor_sync(0xffffffffu, sum, 2);
            l_[rr] += sum;
        }

        uint32_t ph[4][4], pl[4][4];
        #pragma unroll
        for (int jp = 0; jp < 4; jp++) {
            #pragma unroll
            for (int q = 0; q < 4; q++) {
                int nt = 2 * jp + (q >> 1);
                int c0 = (q & 1) * 2;
                float x = S[nt][c0], y = S[nt][c0 + 1];
                __nv_bfloat16 hx = __float2bfloat16_rn(x);
                __nv_bfloat16 hy = __float2bfloat16_rn(y);
                ph[jp][q] = (unsigned)__bfloat16_as_ushort(hx) |
                            ((unsigned)__bfloat16_as_ushort(hy) << 16);
                pl[jp][q] = pack_bf2(x - __bfloat162float(hx), y - __bfloat162float(hy));
            }
        }

        #pragma unroll
        for (int jp = 0; jp < 4; jp++) {
            #pragma unroll
            for (int g = 0; g < 8; g++) {
                uint32_t vh0, vh1, vh2, vh3, vl0, vl1, vl2, vl3;
                uint32_t adh = sbase + (uint32_t)(sVH + (jp * 16 + v_r) * VP + g * 16 + v_n8) * 2;
                LDSM4T(vh0, vh1, vh2, vh3, adh);
                uint32_t adl = sbase + (uint32_t)(sVL + (jp * 16 + v_r) * VP + g * 16 + v_n8) * 2;
                LDSM4T(vl0, vl1, vl2, vl3, adl);
                MMA16816(o[2*g],   ph[jp][0], ph[jp][1], ph[jp][2], ph[jp][3], vh0, vh1);
                MMA16816(o[2*g],   ph[jp][0], ph[jp][1], ph[jp][2], ph[jp][3], vl0, vl1);
                MMA16816(o[2*g],   pl[jp][0], pl[jp][1], pl[jp][2], pl[jp][3], vh0, vh1);
                MMA16816(o[2*g+1], ph[jp][0], ph[jp][1], ph[jp][2], ph[jp][3], vh2, vh3);
                MMA16816(o[2*g+1], ph[jp][0], ph[jp][1], ph[jp][2], ph[jp][3], vl2, vl3);
                MMA16816(o[2*g+1], pl[jp][0], pl[jp][1], pl[jp][2], pl[jp][3], vh2, vh3);
            }
        }
        __syncthreads();
    }

    #pragma unroll
    for (int rr = 0; rr < 2; rr++) {
        float inv = 1.f / l_[rr];
        int srow = qt * 128 + wid * 16 + (lid >> 2) + rr * 8;
        float* xo = g_x + ((size_t)b * SEQ + srow) * ED + h * HD;
        #pragma unroll
        for (int nt = 0; nt < 16; nt++) {
            int col = nt * 8 + (lid & 3) * 2;
            *(float2*)&xo[col] = make_float2(o[nt][rr * 2] * inv, o[nt][rr * 2 + 1] * inv);
        }
    }
}

// ---------------- launch ----------------
extern "C" void kernel_launch(void* const* d_in, const int* in_sizes, int n_in,
                              void* d_out, int out_size) {
    const float* query = (const float*)d_in[0];
    const float* key   = (const float*)d_in[1];
    const float* value = (const float*)d_in[2];
    const float* q_w   = (const float*)d_in[3];
    const float* q_b   = (const float*)d_in[4];
    const float* k_w   = (const float*)d_in[5];
    const float* k_b   = (const float*)d_in[6];
    const float* v_w   = (const float*)d_in[7];
    const float* v_b   = (const float*)d_in[8];
    const float* ln_g  = (const float*)d_in[9];
    const float* ln_b  = (const float*)d_in[10];
    const float* out_w = (const float*)d_in[11];
    const float* out_b = (const float*)d_in[12];

    cudaFuncSetAttribute(attn_mma, cudaFuncAttributeMaxDynamicSharedMemorySize, ATTN_SMEM);
    cudaFuncSetAttribute(gemm_qkv, cudaFuncAttributeMaxDynamicSharedMemorySize, GEMM_SMEM);
    cudaFuncSetAttribute(gemm_out, cudaFuncAttributeMaxDynamicSharedMemorySize, GEMM_SMEM);

    // weight prep (1 launch) + final reduce
    prep_w<<<dim3(256, 4), 256>>>((const float4*)q_w, (const float4*)k_w,
                                  (const float4*)v_w, (const float4*)out_w);
    absmean_final<<<4, 256>>>();

    // all three activation quants (1 launch), then all three projections (1 launch)
    quant_rms<<<dim3(NTOK, 3), 256>>>(query, key, value);
    gemm_qkv<<<384, 256, GEMM_SMEM>>>(q_b, k_b, v_b);

    // attention (HMMA split-bf16, cp.async pipelined)
    attn_mma<<<dim3(SEQ / 128, 16), 256, ATTN_SMEM>>>();

    // layernorm + final bitlinear
    ln_quant<<<NTOK, 256>>>(ln_g, ln_b);
    gemm_out<<<256, 256, GEMM_SMEM>>>(out_b, (float*)d_out);
}